// round 9
// baseline (speedup 1.0000x reference)
#include <cuda_runtime.h>
#include <cuda_fp16.h>
#include <math.h>
#include <stdint.h>

// ---------------- problem constants ----------------
static constexpr int Bn   = 1024;
static constexpr int M3   = 3072;   // B*S
static constexpr int Dd   = 256;
static constexpr int SD   = 768;
static constexpr int OUT1 = 512;
static constexpr int LAT  = 128;

static constexpr size_t N_BE  = (size_t)Bn * 1024;
static constexpr size_t N_BSD = (size_t)M3 * Dd;     // 786432

__device__ float g_scratch[2 * N_BE + 22 * N_BSD + (size_t)Bn * OUT1];
__device__ float g_bias_fused[512];            // [0:256)=b4+b5, [256:512)=b6+b7
__device__ __half g_Wh[16777216];              // bil_W in fp16 (32MB)

__device__ __forceinline__ float sigm(float x) { return 1.0f / (1.0f + expf(-x)); }

__device__ __forceinline__ unsigned tf32r(float x) {
    unsigned r;
    asm("cvt.rna.tf32.f32 %0, %1;" : "=r"(r) : "f"(x));
    return r;
}

__device__ __forceinline__ void mma_tf32(float& c0, float& c1, float& c2, float& c3,
                                         unsigned a0, unsigned a1, unsigned a2, unsigned a3,
                                         unsigned b0, unsigned b1) {
    asm("mma.sync.aligned.m16n8k8.row.col.f32.tf32.tf32.f32 "
        "{%0,%1,%2,%3}, {%4,%5,%6,%7}, {%8,%9}, {%0,%1,%2,%3};"
        : "+f"(c0), "+f"(c1), "+f"(c2), "+f"(c3)
        : "r"(a0), "r"(a1), "r"(a2), "r"(a3), "r"(b0), "r"(b1));
}

__device__ __forceinline__ void mma_f16(float& c0, float& c1, float& c2, float& c3,
                                        unsigned a0, unsigned a1, unsigned a2, unsigned a3,
                                        unsigned b0, unsigned b1) {
    asm("mma.sync.aligned.m16n8k16.row.col.f32.f16.f16.f32 "
        "{%0,%1,%2,%3}, {%4,%5,%6,%7}, {%8,%9}, {%0,%1,%2,%3};"
        : "+f"(c0), "+f"(c1), "+f"(c2), "+f"(c3)
        : "r"(a0), "r"(a1), "r"(a2), "r"(a3), "r"(b0), "r"(b1));
}

__device__ __forceinline__ void cpa16(void* smem_dst, const void* gsrc) {
    unsigned sa = (unsigned)__cvta_generic_to_shared(smem_dst);
    asm volatile("cp.async.cg.shared.global [%0], [%1], 16;" :: "r"(sa), "l"(gsrc));
}

// ---------------- helpers ----------------
__global__ void fuse_bias_kernel(const float* __restrict__ b, float* __restrict__ o)
{
    int i = threadIdx.x;
    o[i]       = b[4 * 256 + i] + b[5 * 256 + i];
    o[256 + i] = b[6 * 256 + i] + b[7 * 256 + i];
}

__global__ void wconv_kernel(const float* __restrict__ W, __half* __restrict__ Wh)
{
    size_t i = ((size_t)blockIdx.x * 256 + threadIdx.x) * 4;
    float4 v = *(const float4*)(W + i);
    *(__half2*)(Wh + i)     = __floats2half2_rn(v.x, v.y);
    *(__half2*)(Wh + i + 2) = __floats2half2_rn(v.z, v.w);
}

// ---------------- fp32 SIMT GEMM, z-batched: 128x64 tile, 256 threads ----------
struct GB32 {
    const float* A[2]; const float* W[2]; const float* b[2]; float* C[2]; int K[2];
};

__global__ void __launch_bounds__(256) gemm_kernel(GB32 P, int M, int N, int flags)
{
    __shared__ __align__(16) float As[16][132];
    __shared__ __align__(16) float Ws[16][68];
    const int z = blockIdx.z;
    const float* A = P.A[z];
    const float* W = P.W[z];
    const float* bias = P.b[z];
    float* C = P.C[z];
    const int K = P.K[z];

    const int tid = threadIdx.x;
    const int tx = tid & 15, ty = tid >> 4;
    const int m0 = blockIdx.y * 128, n0 = blockIdx.x * 64;
    const int lrow = tid >> 2, lk = (tid & 3) << 2;

    const float* Ag0 = A + (size_t)(m0 + lrow) * K + lk;
    const float* Ag1 = A + (size_t)(m0 + lrow + 64) * K + lk;
    const float* Wg  = W + (size_t)(n0 + lrow) * K + lk;

    float acc[8][4] = {};
    for (int kt = 0; kt < K; kt += 16) {
        float4 a0 = *(const float4*)(Ag0 + kt);
        float4 a1 = *(const float4*)(Ag1 + kt);
        float4 w0 = *(const float4*)(Wg + kt);
        As[lk + 0][lrow] = a0.x; As[lk + 1][lrow] = a0.y;
        As[lk + 2][lrow] = a0.z; As[lk + 3][lrow] = a0.w;
        As[lk + 0][lrow + 64] = a1.x; As[lk + 1][lrow + 64] = a1.y;
        As[lk + 2][lrow + 64] = a1.z; As[lk + 3][lrow + 64] = a1.w;
        Ws[lk + 0][lrow] = w0.x; Ws[lk + 1][lrow] = w0.y;
        Ws[lk + 2][lrow] = w0.z; Ws[lk + 3][lrow] = w0.w;
        __syncthreads();
#pragma unroll
        for (int k = 0; k < 16; k++) {
            float ar[8];
            *(float4*)&ar[0] = *(const float4*)&As[k][ty * 8];
            *(float4*)&ar[4] = *(const float4*)&As[k][ty * 8 + 4];
            float4 b = *(const float4*)&Ws[k][tx * 4];
#pragma unroll
            for (int i = 0; i < 8; i++) {
                acc[i][0] = fmaf(ar[i], b.x, acc[i][0]);
                acc[i][1] = fmaf(ar[i], b.y, acc[i][1]);
                acc[i][2] = fmaf(ar[i], b.z, acc[i][2]);
                acc[i][3] = fmaf(ar[i], b.w, acc[i][3]);
            }
        }
        __syncthreads();
    }
#pragma unroll
    for (int i = 0; i < 8; i++) {
        int row = m0 + ty * 8 + i;
#pragma unroll
        for (int j = 0; j < 4; j++) {
            int col = n0 + tx * 4 + j;
            float v = acc[i][j] + bias[col];
            if (flags & 1) v = fmaxf(v, 0.0f);
            C[(size_t)row * N + col] = v;
        }
    }
}

// ---------------- tf32 tensor GEMM v2b: cp.async + EXPLICIT RNA rounding on fragments ----
// flags: bit0 relu ; bit2 sigmul: out = sigm(v * E[row*eld + eoff + col]) ; bit3 N-split
struct GB {
    const float* A[2]; const float* W[2]; const float* W2[2];
    const float* b1[2]; const float* b2[2]; const float* E[2]; float* C[2];
};

__global__ void __launch_bounds__(256) mma_gemm_kernel(
    GB P, int M, int N, int K, int Kx, int flags, int eld, int eoff)
{
    __shared__ __align__(16) float As[2][128][20];
    __shared__ __align__(16) float Ws[2][64][20];
    const int z = blockIdx.z;
    const float* A = P.A[z];
    const float* W = P.W[z];
    const float* W2 = P.W2[z];
    const float* bias = P.b1[z];
    const float* bias2 = P.b2[z];
    const float* E = P.E[z];
    float* C = P.C[z];

    const int tid = threadIdx.x;
    const int lane = tid & 31, wid = tid >> 5;
    const int wm = wid >> 1, wn = wid & 1;     // 4m x 2n
    const int m0 = blockIdx.y * 128, n0 = blockIdx.x * 64;
    const int c4 = lane & 3, lr = lane >> 2;
    const int Kb = K - Kx;
    const bool nsplit = (flags & 8) != 0;

    float c[2][4][4];
#pragma unroll
    for (int mt = 0; mt < 2; mt++)
#pragma unroll
        for (int nt = 0; nt < 4; nt++)
#pragma unroll
            for (int e = 0; e < 4; e++) c[mt][nt][e] = 0.0f;

    const int arow0 = tid >> 2, ach = tid & 3;
    auto issue_tile = [&](int kt) {
        int buf = kt & 1;
        int kbase = kt * 16;
#pragma unroll
        for (int u = 0; u < 2; u++) {
            int chunk = tid + 256 * u;
            int row = chunk >> 2, ch = chunk & 3;
            cpa16(&As[buf][row][ch * 4], A + (size_t)(m0 + row) * K + kbase + ch * 4);
        }
        {
            int row = arow0, ch = ach;
            int k = kbase + ch * 4;
            const float* ws;
            if (nsplit) {
                int n = n0 + row;
                ws = (n < Kx) ? (W + (size_t)n * K + k) : (W2 + (size_t)(n - Kx) * K + k);
            } else {
                ws = (k < Kx) ? (W + (size_t)(n0 + row) * Kx + k)
                              : (W2 + (size_t)(n0 + row) * Kb + (k - Kx));
            }
            cpa16(&Ws[buf][row][ch * 4], ws);
        }
        asm volatile("cp.async.commit_group;");
    };

    issue_tile(0);

    const int ktiles = K >> 4;
    const int rbB = wm * 32 + lr;
    for (int kt = 0; kt < ktiles; kt++) {
        asm volatile("cp.async.wait_group 0;");
        __syncthreads();   // tile(kt) visible; compute(kt-1) done everywhere
        if (kt + 1 < ktiles) issue_tile(kt + 1);
        const int buf = kt & 1;
#pragma unroll
        for (int kk = 0; kk < 16; kk += 8) {
            unsigned a[2][4];
#pragma unroll
            for (int mt = 0; mt < 2; mt++) {
                int rb = rbB + mt * 16;
                // EXPLICIT round-to-nearest tf32 on fragments (unbiased vs in-MMA RZ)
                a[mt][0] = tf32r(As[buf][rb][kk + c4]);
                a[mt][1] = tf32r(As[buf][rb + 8][kk + c4]);
                a[mt][2] = tf32r(As[buf][rb][kk + c4 + 4]);
                a[mt][3] = tf32r(As[buf][rb + 8][kk + c4 + 4]);
            }
#pragma unroll
            for (int nt = 0; nt < 4; nt++) {
                int nb = wn * 32 + nt * 8 + lr;
                unsigned b0 = tf32r(Ws[buf][nb][kk + c4]);
                unsigned b1 = tf32r(Ws[buf][nb][kk + c4 + 4]);
#pragma unroll
                for (int mt = 0; mt < 2; mt++)
                    mma_tf32(c[mt][nt][0], c[mt][nt][1], c[mt][nt][2], c[mt][nt][3],
                             a[mt][0], a[mt][1], a[mt][2], a[mt][3], b0, b1);
            }
        }
        // no trailing sync — next iter's sync gates buffer reuse
    }

#pragma unroll
    for (int mt = 0; mt < 2; mt++) {
#pragma unroll
        for (int nt = 0; nt < 4; nt++) {
            int row = m0 + wm * 32 + mt * 16 + lr;
            int col = n0 + wn * 32 + nt * 8 + c4 * 2;
#pragma unroll
            for (int e = 0; e < 4; e++) {
                int rr = row + (e >> 1) * 8;
                int cc = col + (e & 1);
                float bv = nsplit ? ((cc < Kx) ? bias[cc] : bias2[cc - Kx]) : bias[cc];
                float v = c[mt][nt][e] + bv;
                if (flags & 1) v = fmaxf(v, 0.0f);
                if (flags & 4) v = sigm(v * E[(size_t)rr * eld + eoff + cc]);
                C[(size_t)rr * N + cc] = v;
            }
        }
    }
}

// ---------------- fp16 bilinear v4 (unchanged — numerics of rounds 6/7) ----------------
static constexpr int BIL4_SMEM_BYTES = (128 * 264 + 2 * 64 * 72) * 2;

__global__ void __launch_bounds__(128) bilinear4_kernel(
    const float* __restrict__ cva, const float* __restrict__ cav,
    const __half* __restrict__ Wh, float* __restrict__ part)
{
    extern __shared__ __half sh[];
    __half* s_cav = sh;                // [128][264]
    __half* s_W   = sh + 128 * 264;    // [2][64][72]

    const int tid = threadIdx.x;
    const int lane = tid & 31, wid = tid >> 5;
    const int wm = wid & 1, wn = wid >> 1;   // 2m(64) x 2n(32)
    const int g = lane >> 2, q = lane & 3;
    const int r0 = blockIdx.x * 128, o0 = blockIdx.y * 64;
    const int iBase = blockIdx.z * 64;

    for (int f = tid; f < 8192; f += 128) {
        int row = f >> 6, q4 = f & 63;
        float4 w = *(const float4*)(cav + (size_t)(r0 + row) * 256 + q4 * 4);
        __half* d = s_cav + row * 264 + q4 * 4;
        *(__half2*)(d)     = __floats2half2_rn(w.x, w.y);
        *(__half2*)(d + 2) = __floats2half2_rn(w.z, w.w);
    }

    float c[4][4][4];
#pragma unroll
    for (int mt = 0; mt < 4; mt++)
#pragma unroll
        for (int nt = 0; nt < 4; nt++)
#pragma unroll
            for (int e = 0; e < 4; e++) c[mt][nt][e] = 0.0f;

    auto issue_tile = [&](int it) {
        int i = iBase + (it >> 2), h = it & 3;
        __half* dst0 = s_W + (it & 1) * 64 * 72;
#pragma unroll
        for (int u = 0; u < 4; u++) {
            int cidx = tid + 128 * u;
            int o = cidx >> 3, ch = cidx & 7;
            const __half* src = Wh + (size_t)(o0 + o) * 65536 + (size_t)i * 256 + h * 64 + ch * 8;
            cpa16(dst0 + o * 72 + ch * 8, src);
        }
        asm volatile("cp.async.commit_group;");
    };

    issue_tile(0);

    const int rb = wm * 64 + g;
    const float* cvaB = cva + (size_t)r0 * 256;

    for (int it = 0; it < 256; it++) {
        asm volatile("cp.async.wait_group 0;");
        __syncthreads();
        if (it + 1 < 256) issue_tile(it + 1);

        const __half* wbuf = s_W + (it & 1) * 64 * 72;
        const int ig = iBase + (it >> 2);
        const int h = it & 3;
        __half2 s[8];
#pragma unroll
        for (int mt = 0; mt < 4; mt++) {
            s[2 * mt]     = __half2half2(__float2half_rn(cvaB[(size_t)(rb + mt * 16) * 256 + ig]));
            s[2 * mt + 1] = __half2half2(__float2half_rn(cvaB[(size_t)(rb + mt * 16 + 8) * 256 + ig]));
        }

#pragma unroll
        for (int jc = 0; jc < 4; jc++) {
            const int jlo = h * 64 + jc * 16 + 2 * q;
            const int jhi = jlo + 8;
            __half2 a[4][4];
#pragma unroll
            for (int mt = 0; mt < 4; mt++) {
                int r1 = rb + mt * 16, r2 = r1 + 8;
                a[mt][0] = __hmul2(*(__half2*)&s_cav[r1 * 264 + jlo], s[2 * mt]);
                a[mt][1] = __hmul2(*(__half2*)&s_cav[r2 * 264 + jlo], s[2 * mt + 1]);
                a[mt][2] = __hmul2(*(__half2*)&s_cav[r1 * 264 + jhi], s[2 * mt]);
                a[mt][3] = __hmul2(*(__half2*)&s_cav[r2 * 264 + jhi], s[2 * mt + 1]);
            }
            const int kloc = jc * 16;
#pragma unroll
            for (int nt = 0; nt < 4; nt++) {
                int oc = wn * 32 + nt * 8 + g;
                unsigned b0 = *(const unsigned*)&wbuf[oc * 72 + kloc + 2 * q];
                unsigned b1 = *(const unsigned*)&wbuf[oc * 72 + kloc + 2 * q + 8];
#pragma unroll
                for (int mt = 0; mt < 4; mt++)
                    mma_f16(c[mt][nt][0], c[mt][nt][1], c[mt][nt][2], c[mt][nt][3],
                            *(unsigned*)&a[mt][0], *(unsigned*)&a[mt][1],
                            *(unsigned*)&a[mt][2], *(unsigned*)&a[mt][3], b0, b1);
            }
        }
    }

    float* P = part + (size_t)blockIdx.z * N_BSD;
#pragma unroll
    for (int mt = 0; mt < 4; mt++) {
#pragma unroll
        for (int nt = 0; nt < 4; nt++) {
            int row = r0 + wm * 64 + mt * 16 + g;
            int col = o0 + wn * 32 + nt * 8 + q * 2;
            float* d0 = P + (size_t)row * 256 + col;
            float* d1 = P + (size_t)(row + 8) * 256 + col;
            d0[0] = c[mt][nt][0]; d0[1] = c[mt][nt][1];
            d1[0] = c[mt][nt][2]; d1[1] = c[mt][nt][3];
        }
    }
}

// finish: j = sigm(sum partials); m = tc*j*xv + (1-j)*xa; o1 = m*mv; o2 = m*ma
__global__ void bil_finish_kernel(const float* __restrict__ part,
                                  const float* __restrict__ xv, const float* __restrict__ xa,
                                  const float* __restrict__ tcp,
                                  const float* __restrict__ mv, const float* __restrict__ ma,
                                  float* __restrict__ o1, float* __restrict__ o2)
{
    int i = blockIdx.x * 256 + threadIdx.x;
    float s = part[i] + part[i + N_BSD] + part[i + 2 * N_BSD] + part[i + 3 * N_BSD];
    float j = sigm(s);
    float m = (*tcp) * j * xv[i] + (1.0f - j) * xa[i];
    o1[i] = m * mv[i];
    o2[i] = m * ma[i];
}

// ---------------- attention ----------------
__global__ void __launch_bounds__(256) attn_kernel(
    const float* __restrict__ xv, const float* __restrict__ xa,
    const float* __restrict__ qkv_v, const float* __restrict__ qkv_a,
    float* __restrict__ cat1, float* __restrict__ cat2)
{
    __shared__ float s_x[2][3][256];
    __shared__ float s_q[2][3][256];
    __shared__ float s_k[2][3][256];
    __shared__ float s_sc[4][3][3];
    const int tid = threadIdx.x;
    const size_t base = (size_t)blockIdx.x * 768;
    const size_t base2 = (size_t)blockIdx.x * 1536;
    const size_t qbase = (size_t)blockIdx.x * 3 * 512;

    float* fx = &s_x[0][0][0];
    float* fq = &s_q[0][0][0];
    float* fk = &s_k[0][0][0];
    for (int idx = tid; idx < 768; idx += 256) {
        int s3 = idx >> 8, d = idx & 255;
        size_t qoff = qbase + (size_t)s3 * 512 + d;
        fx[idx] = xv[base + idx]; fx[768 + idx] = xa[base + idx];
        fq[idx] = qkv_v[qoff];        fq[768 + idx] = qkv_a[qoff];
        fk[idx] = qkv_v[qoff + 256];  fk[768 + idx] = qkv_a[qoff + 256];
    }
    __syncthreads();

    const int w = tid >> 5, lane = tid & 31;
    for (int task = w; task < 36; task += 8) {
        int type = task / 9, rem = task % 9, s3 = rem / 3, t3 = rem % 3;
        int qsel = type >> 1;
        int ksel = (type == 0 || type == 3) ? 1 : 0;
        float sum = 0.0f;
        for (int d = lane; d < 256; d += 32) sum += s_q[qsel][s3][d] * s_k[ksel][t3][d];
#pragma unroll
        for (int off = 16; off; off >>= 1) sum += __shfl_down_sync(0xffffffffu, sum, off);
        if (lane == 0) s_sc[type][s3][t3] = sum;
    }
    __syncthreads();

    if (tid < 12) {
        int type = tid / 3, s3 = tid % 3;
        float a = s_sc[type][s3][0], b = s_sc[type][s3][1], c = s_sc[type][s3][2];
        float m = fmaxf(a, fmaxf(b, c));
        float ea = expf(a - m), eb = expf(b - m), ec = expf(c - m);
        float inv = 0.0625f / (ea + eb + ec);
        s_sc[type][s3][0] = ea * inv; s_sc[type][s3][1] = eb * inv; s_sc[type][s3][2] = ec * inv;
    }
    __syncthreads();

    for (int idx = tid; idx < 3072; idx += 256) {
        int type = idx / 768, rem = idx % 768;
        int s3 = rem >> 8, d = rem & 255;
        int xsel = (type == 0 || type == 3) ? 1 : 0;
        float v = s_sc[type][s3][0] * s_x[xsel][0][d]
                + s_sc[type][s3][1] * s_x[xsel][1][d]
                + s_sc[type][s3][2] * s_x[xsel][2][d];
        float* dst = (type < 2) ? cat1 : cat2;
        dst[base2 + (size_t)s3 * 512 + ((type & 1) ? 256 : 0) + d] = v;
    }
}

// ---------------- classifier ----------------
__global__ void __launch_bounds__(256) cls_kernel(
    const float* __restrict__ F, const float* __restrict__ W1,
    const float* __restrict__ W2, float* __restrict__ P)
{
    __shared__ float s_f[8][128];
    __shared__ float s_w1[32][129];
    __shared__ float s_w2[320];
    __shared__ float s_h[8][32];
    const int tid = threadIdx.x;
    const int r0 = blockIdx.x * 8;
    for (int idx = tid; idx < 1024; idx += 256) s_f[idx >> 7][idx & 127] = F[(size_t)r0 * 128 + idx];
    for (int idx = tid; idx < 4096; idx += 256) s_w1[idx >> 7][idx & 127] = W1[idx];
    for (int idx = tid; idx < 320; idx += 256) s_w2[idx] = W2[idx];
    __syncthreads();
    const int w = tid >> 5, lane = tid & 31;
    float h = 0.0f;
#pragma unroll 8
    for (int d = 0; d < 128; d++) h = fmaf(s_f[w][d], s_w1[lane][d], h);
    s_h[w][lane] = fmaxf(h, 0.0f);
    __syncwarp();
    if (lane < 10) {
        float p = 0.0f;
#pragma unroll
        for (int k = 0; k < 32; k++) p = fmaf(s_h[w][k], s_w2[lane * 32 + k], p);
        P[(size_t)(r0 + w) * 10 + lane] = p;
    }
}

// ---------------- host ----------------
extern "C" void kernel_launch(void* const* d_in, const int* in_sizes, int n_in,
                              void* d_out, int out_size)
{
    const float* img    = (const float*)d_in[0];
    const float* audio  = (const float*)d_in[1];
    const float* vis_W  = (const float*)d_in[2];
    const float* vis_b  = (const float*)d_in[3];
    const float* aud_W  = (const float*)d_in[4];
    const float* aud_b  = (const float*)d_in[5];
    const float* msv_W  = (const float*)d_in[6];
    const float* msv_b  = (const float*)d_in[7];
    const float* msa_W  = (const float*)d_in[8];
    const float* msa_b  = (const float*)d_in[9];
    const float* mmfaW  = (const float*)d_in[10];
    const float* mmfaB  = (const float*)d_in[11];
    const float* bilW   = (const float*)d_in[12];
    const float* t_c    = (const float*)d_in[13];
    const float* out_W1 = (const float*)d_in[14];
    const float* out_b1 = (const float*)d_in[15];
    const float* out_W2 = (const float*)d_in[16];
    const float* out_b2 = (const float*)d_in[17];
    const float* clsvW1 = (const float*)d_in[18];
    const float* clsvW2 = (const float*)d_in[19];
    const float* clsaW1 = (const float*)d_in[20];
    const float* clsaW2 = (const float*)d_in[21];

    float* S = nullptr;
    cudaGetSymbolAddress((void**)&S, g_scratch);
    float* p_bf = nullptr;
    cudaGetSymbolAddress((void**)&p_bf, g_bias_fused);
    __half* p_Wh = nullptr;
    cudaGetSymbolAddress((void**)&p_Wh, g_Wh);

    float* p_vis  = S;
    float* p_aud  = p_vis + N_BE;
    float* p_vms  = p_aud + N_BE;
    float* p_ams  = p_vms + N_BSD;
    float* p_qkv  = p_ams + N_BSD;        // [3072][512] (qv | kv)
    float* p_qka  = p_qkv + 2 * N_BSD;    // [3072][512] (qa | ka)
    float* p_cat1 = p_qka + 2 * N_BSD;    // [3072][512]
    float* p_cat2 = p_cat1 + 2 * N_BSD;   // [3072][512]
    float* p_cva  = p_cat2 + 2 * N_BSD;
    float* p_cav  = p_cva + N_BSD;
    float* p_bp   = p_cav + N_BSD;        // 4 x [3072][256]
    float* p_xv   = p_bp  + 4 * N_BSD;
    float* p_xa   = p_xv  + N_BSD;
    float* p_ov   = p_xa  + N_BSD;        // ov/oa contiguous -> [2048][768]
    float* p_oa   = p_ov  + N_BSD;
    float* p_h    = p_oa  + N_BSD;        // [2048][512]

    const int nBlk = (int)(N_BSD / 256);

    cudaFuncSetAttribute(bilinear4_kernel,
                         cudaFuncAttributeMaxDynamicSharedMemorySize, BIL4_SMEM_BYTES);

    fuse_bias_kernel<<<1, 256>>>(mmfaB, p_bf);
    wconv_kernel<<<16384, 256>>>(bilW, p_Wh);
    float* p_b45 = p_bf;
    float* p_b67 = p_bf + 256;

    auto run_mmfa = [&](const float* xv, const float* xa,
                        const float* mv, const float* ma, float* o1, float* o2) {
        GB qk;
        qk.A[0] = xv;  qk.W[0] = mmfaW + 0 * 65536; qk.W2[0] = mmfaW + 2 * 65536;
        qk.b1[0] = mmfaB + 0 * 256; qk.b2[0] = mmfaB + 2 * 256; qk.E[0] = xv;  qk.C[0] = p_qkv;
        qk.A[1] = xa;  qk.W[1] = mmfaW + 1 * 65536; qk.W2[1] = mmfaW + 3 * 65536;
        qk.b1[1] = mmfaB + 1 * 256; qk.b2[1] = mmfaB + 3 * 256; qk.E[1] = xa;  qk.C[1] = p_qka;
        mma_gemm_kernel<<<dim3(512 / 64, M3 / 128, 2), 256>>>(qk, M3, 512, Dd, 256, 8, 0, 0);

        attn_kernel<<<Bn, 256>>>(xv, xa, p_qkv, p_qka, p_cat1, p_cat2);

        GB cc;
        cc.A[0] = p_cat1; cc.W[0] = mmfaW + 4 * 65536; cc.W2[0] = mmfaW + 5 * 65536;
        cc.b1[0] = p_b45; cc.b2[0] = p_b45; cc.E[0] = p_cat1; cc.C[0] = p_cva;
        cc.A[1] = p_cat2; cc.W[1] = mmfaW + 6 * 65536; cc.W2[1] = mmfaW + 7 * 65536;
        cc.b1[1] = p_b67; cc.b2[1] = p_b67; cc.E[1] = p_cat2; cc.C[1] = p_cav;
        mma_gemm_kernel<<<dim3(256 / 64, M3 / 128, 2), 256>>>(cc, M3, Dd, 512, 256, 4, 512, 256);

        bilinear4_kernel<<<dim3(24, 4, 4), 128, BIL4_SMEM_BYTES>>>(p_cva, p_cav, p_Wh, p_bp);
        bil_finish_kernel<<<nBlk, 256>>>(p_bp, xv, xa, t_c, mv, ma, o1, o2);
    };

    // encoders (vis||aud) + multi-scale (z-batched), fp32 SIMT
    {
        GB32 e;
        e.A[0] = img;   e.W[0] = vis_W; e.b[0] = vis_b; e.C[0] = p_vis; e.K[0] = 4096;
        e.A[1] = audio; e.W[1] = aud_W; e.b[1] = aud_b; e.C[1] = p_aud; e.K[1] = 1024;
        gemm_kernel<<<dim3(16, 8, 2), 256>>>(e, Bn, 1024, 1);

        GB32 m;
        m.A[0] = p_vis; m.W[0] = msv_W; m.b[0] = msv_b; m.C[0] = p_vms; m.K[0] = 1024;
        m.A[1] = p_aud; m.W[1] = msa_W; m.b[1] = msa_b; m.C[1] = p_ams; m.K[1] = 1024;
        gemm_kernel<<<dim3(12, 8, 2), 256>>>(m, Bn, SD, 1);
    }

    // MMfa 1: xv2 = M1*vms, xa2 = M1*ams ; MMfa 2: ov = M2*vms, oa = M2*ams
    run_mmfa(p_vms, p_ams, p_vms, p_ams, p_xv, p_xa);
    run_mmfa(p_xv, p_xa, p_vms, p_ams, p_ov, p_oa);

    float* out = (float*)d_out;
    float* fv = out;
    float* fa = out + (size_t)Bn * LAT;
    float* pv = fa + (size_t)Bn * LAT;
    float* pa = pv + (size_t)Bn * 10;

    // out_layer M-batched over (ov||oa) -> (fv||fa)
    {
        GB o1;
        o1.A[0] = o1.A[1] = p_ov; o1.W[0] = o1.W[1] = out_W1; o1.W2[0] = o1.W2[1] = out_W1;
        o1.b1[0] = o1.b1[1] = out_b1; o1.b2[0] = o1.b2[1] = out_b1;
        o1.E[0] = o1.E[1] = p_ov; o1.C[0] = o1.C[1] = p_h;
        mma_gemm_kernel<<<dim3(OUT1 / 64, 2 * Bn / 128, 1), 256>>>(o1, 2 * Bn, OUT1, SD, SD, 1, 0, 0);

        GB o2;
        o2.A[0] = o2.A[1] = p_h; o2.W[0] = o2.W[1] = out_W2; o2.W2[0] = o2.W2[1] = out_W2;
        o2.b1[0] = o2.b1[1] = out_b2; o2.b2[0] = o2.b2[1] = out_b2;
        o2.E[0] = o2.E[1] = p_h; o2.C[0] = o2.C[1] = fv;
        mma_gemm_kernel<<<dim3(LAT / 64, 2 * Bn / 128, 1), 256>>>(o2, 2 * Bn, LAT, OUT1, OUT1, 0, 0, 0);
    }

    cls_kernel<<<Bn / 8, 256>>>(fv, clsvW1, clsvW2, pv);
    cls_kernel<<<Bn / 8, 256>>>(fa, clsaW1, clsaW2, pa);
}

// round 10
// speedup vs baseline: 1.0034x; 1.0034x over previous
#include <cuda_runtime.h>
#include <cuda_fp16.h>
#include <math.h>
#include <stdint.h>

// ---------------- problem constants ----------------
static constexpr int Bn   = 1024;
static constexpr int M3   = 3072;   // B*S
static constexpr int Dd   = 256;
static constexpr int SD   = 768;
static constexpr int OUT1 = 512;
static constexpr int LAT  = 128;

static constexpr size_t N_BE  = (size_t)Bn * 1024;
static constexpr size_t N_BSD = (size_t)M3 * Dd;     // 786432

__device__ float g_scratch[2 * N_BE + 22 * N_BSD + (size_t)Bn * OUT1];
__device__ float g_bias_fused[512];            // [0:256)=b4+b5, [256:512)=b6+b7
__device__ __half g_Wh[16777216];              // bil_W in fp16 (32MB)

__device__ __forceinline__ float sigm(float x) { return 1.0f / (1.0f + expf(-x)); }

__device__ __forceinline__ unsigned tf32r(float x) {
    unsigned r;
    asm("cvt.rna.tf32.f32 %0, %1;" : "=r"(r) : "f"(x));
    return r;
}

__device__ __forceinline__ void mma_tf32(float& c0, float& c1, float& c2, float& c3,
                                         unsigned a0, unsigned a1, unsigned a2, unsigned a3,
                                         unsigned b0, unsigned b1) {
    asm("mma.sync.aligned.m16n8k8.row.col.f32.tf32.tf32.f32 "
        "{%0,%1,%2,%3}, {%4,%5,%6,%7}, {%8,%9}, {%0,%1,%2,%3};"
        : "+f"(c0), "+f"(c1), "+f"(c2), "+f"(c3)
        : "r"(a0), "r"(a1), "r"(a2), "r"(a3), "r"(b0), "r"(b1));
}

__device__ __forceinline__ void mma_f16(float& c0, float& c1, float& c2, float& c3,
                                        unsigned a0, unsigned a1, unsigned a2, unsigned a3,
                                        unsigned b0, unsigned b1) {
    asm("mma.sync.aligned.m16n8k16.row.col.f32.f16.f16.f32 "
        "{%0,%1,%2,%3}, {%4,%5,%6,%7}, {%8,%9}, {%0,%1,%2,%3};"
        : "+f"(c0), "+f"(c1), "+f"(c2), "+f"(c3)
        : "r"(a0), "r"(a1), "r"(a2), "r"(a3), "r"(b0), "r"(b1));
}

__device__ __forceinline__ void cpa16(void* smem_dst, const void* gsrc) {
    unsigned sa = (unsigned)__cvta_generic_to_shared(smem_dst);
    asm volatile("cp.async.cg.shared.global [%0], [%1], 16;" :: "r"(sa), "l"(gsrc));
}

// ---------------- helpers ----------------
__global__ void fuse_bias_kernel(const float* __restrict__ b, float* __restrict__ o)
{
    int i = threadIdx.x;
    o[i]       = b[4 * 256 + i] + b[5 * 256 + i];
    o[256 + i] = b[6 * 256 + i] + b[7 * 256 + i];
}

__global__ void wconv_kernel(const float* __restrict__ W, __half* __restrict__ Wh)
{
    size_t i = ((size_t)blockIdx.x * 256 + threadIdx.x) * 4;
    float4 v = *(const float4*)(W + i);
    *(__half2*)(Wh + i)     = __floats2half2_rn(v.x, v.y);
    *(__half2*)(Wh + i + 2) = __floats2half2_rn(v.z, v.w);
}

// ---------------- fp32 SIMT GEMM, z-batched: 128x64 tile, 256 threads ----------
struct GB32 {
    const float* A[2]; const float* W[2]; const float* b[2]; float* C[2]; int K[2];
};

__global__ void __launch_bounds__(256) gemm_kernel(GB32 P, int M, int N, int flags)
{
    __shared__ __align__(16) float As[16][132];
    __shared__ __align__(16) float Ws[16][68];
    const int z = blockIdx.z;
    const float* A = P.A[z];
    const float* W = P.W[z];
    const float* bias = P.b[z];
    float* C = P.C[z];
    const int K = P.K[z];

    const int tid = threadIdx.x;
    const int tx = tid & 15, ty = tid >> 4;
    const int m0 = blockIdx.y * 128, n0 = blockIdx.x * 64;
    const int lrow = tid >> 2, lk = (tid & 3) << 2;

    const float* Ag0 = A + (size_t)(m0 + lrow) * K + lk;
    const float* Ag1 = A + (size_t)(m0 + lrow + 64) * K + lk;
    const float* Wg  = W + (size_t)(n0 + lrow) * K + lk;

    float acc[8][4] = {};
    for (int kt = 0; kt < K; kt += 16) {
        float4 a0 = *(const float4*)(Ag0 + kt);
        float4 a1 = *(const float4*)(Ag1 + kt);
        float4 w0 = *(const float4*)(Wg + kt);
        As[lk + 0][lrow] = a0.x; As[lk + 1][lrow] = a0.y;
        As[lk + 2][lrow] = a0.z; As[lk + 3][lrow] = a0.w;
        As[lk + 0][lrow + 64] = a1.x; As[lk + 1][lrow + 64] = a1.y;
        As[lk + 2][lrow + 64] = a1.z; As[lk + 3][lrow + 64] = a1.w;
        Ws[lk + 0][lrow] = w0.x; Ws[lk + 1][lrow] = w0.y;
        Ws[lk + 2][lrow] = w0.z; Ws[lk + 3][lrow] = w0.w;
        __syncthreads();
#pragma unroll
        for (int k = 0; k < 16; k++) {
            float ar[8];
            *(float4*)&ar[0] = *(const float4*)&As[k][ty * 8];
            *(float4*)&ar[4] = *(const float4*)&As[k][ty * 8 + 4];
            float4 b = *(const float4*)&Ws[k][tx * 4];
#pragma unroll
            for (int i = 0; i < 8; i++) {
                acc[i][0] = fmaf(ar[i], b.x, acc[i][0]);
                acc[i][1] = fmaf(ar[i], b.y, acc[i][1]);
                acc[i][2] = fmaf(ar[i], b.z, acc[i][2]);
                acc[i][3] = fmaf(ar[i], b.w, acc[i][3]);
            }
        }
        __syncthreads();
    }
#pragma unroll
    for (int i = 0; i < 8; i++) {
        int row = m0 + ty * 8 + i;
#pragma unroll
        for (int j = 0; j < 4; j++) {
            int col = n0 + tx * 4 + j;
            float v = acc[i][j] + bias[col];
            if (flags & 1) v = fmaxf(v, 0.0f);
            C[(size_t)row * N + col] = v;
        }
    }
}

// ---------------- tf32 tensor GEMM v2b: cp.async + EXPLICIT RNA rounding ------------
// flags: bit0 relu ; bit2 sigmul: out = sigm(v * E[row*eld + eoff + col]) ; bit3 N-split
struct GB {
    const float* A[2]; const float* W[2]; const float* W2[2];
    const float* b1[2]; const float* b2[2]; const float* E[2]; float* C[2];
};

__global__ void __launch_bounds__(256) mma_gemm_kernel(
    GB P, int M, int N, int K, int Kx, int flags, int eld, int eoff)
{
    __shared__ __align__(16) float As[2][128][20];
    __shared__ __align__(16) float Ws[2][64][20];
    const int z = blockIdx.z;
    const float* A = P.A[z];
    const float* W = P.W[z];
    const float* W2 = P.W2[z];
    const float* bias = P.b1[z];
    const float* bias2 = P.b2[z];
    const float* E = P.E[z];
    float* C = P.C[z];

    const int tid = threadIdx.x;
    const int lane = tid & 31, wid = tid >> 5;
    const int wm = wid >> 1, wn = wid & 1;     // 4m x 2n
    const int m0 = blockIdx.y * 128, n0 = blockIdx.x * 64;
    const int c4 = lane & 3, lr = lane >> 2;
    const int Kb = K - Kx;
    const bool nsplit = (flags & 8) != 0;

    float c[2][4][4];
#pragma unroll
    for (int mt = 0; mt < 2; mt++)
#pragma unroll
        for (int nt = 0; nt < 4; nt++)
#pragma unroll
            for (int e = 0; e < 4; e++) c[mt][nt][e] = 0.0f;

    const int arow0 = tid >> 2, ach = tid & 3;
    auto issue_tile = [&](int kt) {
        int buf = kt & 1;
        int kbase = kt * 16;
#pragma unroll
        for (int u = 0; u < 2; u++) {
            int chunk = tid + 256 * u;
            int row = chunk >> 2, ch = chunk & 3;
            cpa16(&As[buf][row][ch * 4], A + (size_t)(m0 + row) * K + kbase + ch * 4);
        }
        {
            int row = arow0, ch = ach;
            int k = kbase + ch * 4;
            const float* ws;
            if (nsplit) {
                int n = n0 + row;
                ws = (n < Kx) ? (W + (size_t)n * K + k) : (W2 + (size_t)(n - Kx) * K + k);
            } else {
                ws = (k < Kx) ? (W + (size_t)(n0 + row) * Kx + k)
                              : (W2 + (size_t)(n0 + row) * Kb + (k - Kx));
            }
            cpa16(&Ws[buf][row][ch * 4], ws);
        }
        asm volatile("cp.async.commit_group;");
    };

    issue_tile(0);

    const int ktiles = K >> 4;
    const int rbB = wm * 32 + lr;
    for (int kt = 0; kt < ktiles; kt++) {
        asm volatile("cp.async.wait_group 0;");
        __syncthreads();
        if (kt + 1 < ktiles) issue_tile(kt + 1);
        const int buf = kt & 1;
#pragma unroll
        for (int kk = 0; kk < 16; kk += 8) {
            unsigned a[2][4];
#pragma unroll
            for (int mt = 0; mt < 2; mt++) {
                int rb = rbB + mt * 16;
                a[mt][0] = tf32r(As[buf][rb][kk + c4]);
                a[mt][1] = tf32r(As[buf][rb + 8][kk + c4]);
                a[mt][2] = tf32r(As[buf][rb][kk + c4 + 4]);
                a[mt][3] = tf32r(As[buf][rb + 8][kk + c4 + 4]);
            }
#pragma unroll
            for (int nt = 0; nt < 4; nt++) {
                int nb = wn * 32 + nt * 8 + lr;
                unsigned b0 = tf32r(Ws[buf][nb][kk + c4]);
                unsigned b1 = tf32r(Ws[buf][nb][kk + c4 + 4]);
#pragma unroll
                for (int mt = 0; mt < 2; mt++)
                    mma_tf32(c[mt][nt][0], c[mt][nt][1], c[mt][nt][2], c[mt][nt][3],
                             a[mt][0], a[mt][1], a[mt][2], a[mt][3], b0, b1);
            }
        }
    }

#pragma unroll
    for (int mt = 0; mt < 2; mt++) {
#pragma unroll
        for (int nt = 0; nt < 4; nt++) {
            int row = m0 + wm * 32 + mt * 16 + lr;
            int col = n0 + wn * 32 + nt * 8 + c4 * 2;
#pragma unroll
            for (int e = 0; e < 4; e++) {
                int rr = row + (e >> 1) * 8;
                int cc = col + (e & 1);
                float bv = nsplit ? ((cc < Kx) ? bias[cc] : bias2[cc - Kx]) : bias[cc];
                float v = c[mt][nt][e] + bv;
                if (flags & 1) v = fmaxf(v, 0.0f);
                if (flags & 4) v = sigm(v * E[(size_t)rr * eld + eoff + cc]);
                C[(size_t)rr * N + cc] = v;
            }
        }
    }
}

// ---------------- fp16 bilinear v5: 256 thr / 8 warps, 128x128 tile, 1 wave ----------
// grid (24, 2, 4): r-block 128, o-block 128, i-range 64. warps 2m(64) x 4n(32).
// smem: s_cav [128][264] + s_W [2][128][72] fp16 = 104448 B -> 2 blocks/SM -> 296 slots
static constexpr int BIL5_SMEM_BYTES = (128 * 264 + 2 * 128 * 72) * 2;

__global__ void __launch_bounds__(256) bilinear5_kernel(
    const float* __restrict__ cva, const float* __restrict__ cav,
    const __half* __restrict__ Wh, float* __restrict__ part)
{
    extern __shared__ __half sh[];
    __half* s_cav = sh;                // [128][264]
    __half* s_W   = sh + 128 * 264;    // [2][128][72]

    const int tid = threadIdx.x;
    const int lane = tid & 31, wid = tid >> 5;
    const int wm = wid & 1, wn = wid >> 1;   // 2m(64) x 4n(32)
    const int g = lane >> 2, q = lane & 3;
    const int r0 = blockIdx.x * 128, o0 = blockIdx.y * 128;
    const int iBase = blockIdx.z * 64;

    for (int f = tid; f < 8192; f += 256) {
        int row = f >> 6, q4 = f & 63;
        float4 w = *(const float4*)(cav + (size_t)(r0 + row) * 256 + q4 * 4);
        __half* d = s_cav + row * 264 + q4 * 4;
        *(__half2*)(d)     = __floats2half2_rn(w.x, w.y);
        *(__half2*)(d + 2) = __floats2half2_rn(w.z, w.w);
    }

    float c[4][4][4];
#pragma unroll
    for (int mt = 0; mt < 4; mt++)
#pragma unroll
        for (int nt = 0; nt < 4; nt++)
#pragma unroll
            for (int e = 0; e < 4; e++) c[mt][nt][e] = 0.0f;

    // cp.async W tile: 128 o x 64 j halves = 16KB = 1024 x 16B chunks, 4 per thread
    auto issue_tile = [&](int it) {
        int i = iBase + (it >> 2), h = it & 3;
        __half* dst0 = s_W + (it & 1) * 128 * 72;
#pragma unroll
        for (int u = 0; u < 4; u++) {
            int cidx = tid + 256 * u;          // 0..1023
            int o = cidx >> 3, ch = cidx & 7;
            const __half* src = Wh + (size_t)(o0 + o) * 65536 + (size_t)i * 256 + h * 64 + ch * 8;
            cpa16(dst0 + o * 72 + ch * 8, src);
        }
        asm volatile("cp.async.commit_group;");
    };

    issue_tile(0);

    const int rb = wm * 64 + g;
    const float* cvaB = cva + (size_t)r0 * 256;

    for (int it = 0; it < 256; it++) {
        asm volatile("cp.async.wait_group 0;");
        __syncthreads();   // tile(it) + s_cav visible; compute(it-1) done everywhere
        if (it + 1 < 256) issue_tile(it + 1);

        const __half* wbuf = s_W + (it & 1) * 128 * 72;
        const int ig = iBase + (it >> 2);
        const int h = it & 3;
        __half2 s[8];
#pragma unroll
        for (int mt = 0; mt < 4; mt++) {
            s[2 * mt]     = __half2half2(__float2half_rn(cvaB[(size_t)(rb + mt * 16) * 256 + ig]));
            s[2 * mt + 1] = __half2half2(__float2half_rn(cvaB[(size_t)(rb + mt * 16 + 8) * 256 + ig]));
        }

#pragma unroll
        for (int jc = 0; jc < 4; jc++) {
            const int jlo = h * 64 + jc * 16 + 2 * q;
            const int jhi = jlo + 8;
            __half2 a[4][4];
#pragma unroll
            for (int mt = 0; mt < 4; mt++) {
                int r1 = rb + mt * 16, r2 = r1 + 8;
                a[mt][0] = __hmul2(*(__half2*)&s_cav[r1 * 264 + jlo], s[2 * mt]);
                a[mt][1] = __hmul2(*(__half2*)&s_cav[r2 * 264 + jlo], s[2 * mt + 1]);
                a[mt][2] = __hmul2(*(__half2*)&s_cav[r1 * 264 + jhi], s[2 * mt]);
                a[mt][3] = __hmul2(*(__half2*)&s_cav[r2 * 264 + jhi], s[2 * mt + 1]);
            }
            const int kloc = jc * 16;
#pragma unroll
            for (int nt = 0; nt < 4; nt++) {
                int oc = wn * 32 + nt * 8 + g;
                unsigned b0 = *(const unsigned*)&wbuf[oc * 72 + kloc + 2 * q];
                unsigned b1 = *(const unsigned*)&wbuf[oc * 72 + kloc + 2 * q + 8];
#pragma unroll
                for (int mt = 0; mt < 4; mt++)
                    mma_f16(c[mt][nt][0], c[mt][nt][1], c[mt][nt][2], c[mt][nt][3],
                            *(unsigned*)&a[mt][0], *(unsigned*)&a[mt][1],
                            *(unsigned*)&a[mt][2], *(unsigned*)&a[mt][3], b0, b1);
            }
        }
    }

    float* P = part + (size_t)blockIdx.z * N_BSD;
#pragma unroll
    for (int mt = 0; mt < 4; mt++) {
#pragma unroll
        for (int nt = 0; nt < 4; nt++) {
            int row = r0 + wm * 64 + mt * 16 + g;
            int col = o0 + wn * 32 + nt * 8 + q * 2;
            float* d0 = P + (size_t)row * 256 + col;
            float* d1 = P + (size_t)(row + 8) * 256 + col;
            d0[0] = c[mt][nt][0]; d0[1] = c[mt][nt][1];
            d1[0] = c[mt][nt][2]; d1[1] = c[mt][nt][3];
        }
    }
}

// finish: j = sigm(sum partials); m = tc*j*xv + (1-j)*xa; o1 = m*mv; o2 = m*ma
__global__ void bil_finish_kernel(const float* __restrict__ part,
                                  const float* __restrict__ xv, const float* __restrict__ xa,
                                  const float* __restrict__ tcp,
                                  const float* __restrict__ mv, const float* __restrict__ ma,
                                  float* __restrict__ o1, float* __restrict__ o2)
{
    int i = blockIdx.x * 256 + threadIdx.x;
    float s = part[i] + part[i + N_BSD] + part[i + 2 * N_BSD] + part[i + 3 * N_BSD];
    float j = sigm(s);
    float m = (*tcp) * j * xv[i] + (1.0f - j) * xa[i];
    o1[i] = m * mv[i];
    o2[i] = m * ma[i];
}

// ---------------- attention ----------------
__global__ void __launch_bounds__(256) attn_kernel(
    const float* __restrict__ xv, const float* __restrict__ xa,
    const float* __restrict__ qkv_v, const float* __restrict__ qkv_a,
    float* __restrict__ cat1, float* __restrict__ cat2)
{
    __shared__ float s_x[2][3][256];
    __shared__ float s_q[2][3][256];
    __shared__ float s_k[2][3][256];
    __shared__ float s_sc[4][3][3];
    const int tid = threadIdx.x;
    const size_t base = (size_t)blockIdx.x * 768;
    const size_t base2 = (size_t)blockIdx.x * 1536;
    const size_t qbase = (size_t)blockIdx.x * 3 * 512;

    float* fx = &s_x[0][0][0];
    float* fq = &s_q[0][0][0];
    float* fk = &s_k[0][0][0];
    for (int idx = tid; idx < 768; idx += 256) {
        int s3 = idx >> 8, d = idx & 255;
        size_t qoff = qbase + (size_t)s3 * 512 + d;
        fx[idx] = xv[base + idx]; fx[768 + idx] = xa[base + idx];
        fq[idx] = qkv_v[qoff];        fq[768 + idx] = qkv_a[qoff];
        fk[idx] = qkv_v[qoff + 256];  fk[768 + idx] = qkv_a[qoff + 256];
    }
    __syncthreads();

    const int w = tid >> 5, lane = tid & 31;
    for (int task = w; task < 36; task += 8) {
        int type = task / 9, rem = task % 9, s3 = rem / 3, t3 = rem % 3;
        int qsel = type >> 1;
        int ksel = (type == 0 || type == 3) ? 1 : 0;
        float sum = 0.0f;
        for (int d = lane; d < 256; d += 32) sum += s_q[qsel][s3][d] * s_k[ksel][t3][d];
#pragma unroll
        for (int off = 16; off; off >>= 1) sum += __shfl_down_sync(0xffffffffu, sum, off);
        if (lane == 0) s_sc[type][s3][t3] = sum;
    }
    __syncthreads();

    if (tid < 12) {
        int type = tid / 3, s3 = tid % 3;
        float a = s_sc[type][s3][0], b = s_sc[type][s3][1], c = s_sc[type][s3][2];
        float m = fmaxf(a, fmaxf(b, c));
        float ea = expf(a - m), eb = expf(b - m), ec = expf(c - m);
        float inv = 0.0625f / (ea + eb + ec);
        s_sc[type][s3][0] = ea * inv; s_sc[type][s3][1] = eb * inv; s_sc[type][s3][2] = ec * inv;
    }
    __syncthreads();

    for (int idx = tid; idx < 3072; idx += 256) {
        int type = idx / 768, rem = idx % 768;
        int s3 = rem >> 8, d = rem & 255;
        int xsel = (type == 0 || type == 3) ? 1 : 0;
        float v = s_sc[type][s3][0] * s_x[xsel][0][d]
                + s_sc[type][s3][1] * s_x[xsel][1][d]
                + s_sc[type][s3][2] * s_x[xsel][2][d];
        float* dst = (type < 2) ? cat1 : cat2;
        dst[base2 + (size_t)s3 * 512 + ((type & 1) ? 256 : 0) + d] = v;
    }
}

// ---------------- classifier ----------------
__global__ void __launch_bounds__(256) cls_kernel(
    const float* __restrict__ F, const float* __restrict__ W1,
    const float* __restrict__ W2, float* __restrict__ P)
{
    __shared__ float s_f[8][128];
    __shared__ float s_w1[32][129];
    __shared__ float s_w2[320];
    __shared__ float s_h[8][32];
    const int tid = threadIdx.x;
    const int r0 = blockIdx.x * 8;
    for (int idx = tid; idx < 1024; idx += 256) s_f[idx >> 7][idx & 127] = F[(size_t)r0 * 128 + idx];
    for (int idx = tid; idx < 4096; idx += 256) s_w1[idx >> 7][idx & 127] = W1[idx];
    for (int idx = tid; idx < 320; idx += 256) s_w2[idx] = W2[idx];
    __syncthreads();
    const int w = tid >> 5, lane = tid & 31;
    float h = 0.0f;
#pragma unroll 8
    for (int d = 0; d < 128; d++) h = fmaf(s_f[w][d], s_w1[lane][d], h);
    s_h[w][lane] = fmaxf(h, 0.0f);
    __syncwarp();
    if (lane < 10) {
        float p = 0.0f;
#pragma unroll
        for (int k = 0; k < 32; k++) p = fmaf(s_h[w][k], s_w2[lane * 32 + k], p);
        P[(size_t)(r0 + w) * 10 + lane] = p;
    }
}

// ---------------- host ----------------
extern "C" void kernel_launch(void* const* d_in, const int* in_sizes, int n_in,
                              void* d_out, int out_size)
{
    const float* img    = (const float*)d_in[0];
    const float* audio  = (const float*)d_in[1];
    const float* vis_W  = (const float*)d_in[2];
    const float* vis_b  = (const float*)d_in[3];
    const float* aud_W  = (const float*)d_in[4];
    const float* aud_b  = (const float*)d_in[5];
    const float* msv_W  = (const float*)d_in[6];
    const float* msv_b  = (const float*)d_in[7];
    const float* msa_W  = (const float*)d_in[8];
    const float* msa_b  = (const float*)d_in[9];
    const float* mmfaW  = (const float*)d_in[10];
    const float* mmfaB  = (const float*)d_in[11];
    const float* bilW   = (const float*)d_in[12];
    const float* t_c    = (const float*)d_in[13];
    const float* out_W1 = (const float*)d_in[14];
    const float* out_b1 = (const float*)d_in[15];
    const float* out_W2 = (const float*)d_in[16];
    const float* out_b2 = (const float*)d_in[17];
    const float* clsvW1 = (const float*)d_in[18];
    const float* clsvW2 = (const float*)d_in[19];
    const float* clsaW1 = (const float*)d_in[20];
    const float* clsaW2 = (const float*)d_in[21];

    float* S = nullptr;
    cudaGetSymbolAddress((void**)&S, g_scratch);
    float* p_bf = nullptr;
    cudaGetSymbolAddress((void**)&p_bf, g_bias_fused);
    __half* p_Wh = nullptr;
    cudaGetSymbolAddress((void**)&p_Wh, g_Wh);

    float* p_vis  = S;
    float* p_aud  = p_vis + N_BE;
    float* p_vms  = p_aud + N_BE;
    float* p_ams  = p_vms + N_BSD;
    float* p_qkv  = p_ams + N_BSD;        // [3072][512] (qv | kv)
    float* p_qka  = p_qkv + 2 * N_BSD;    // [3072][512] (qa | ka)
    float* p_cat1 = p_qka + 2 * N_BSD;    // [3072][512]
    float* p_cat2 = p_cat1 + 2 * N_BSD;   // [3072][512]
    float* p_cva  = p_cat2 + 2 * N_BSD;
    float* p_cav  = p_cva + N_BSD;
    float* p_bp   = p_cav + N_BSD;        // 4 x [3072][256]
    float* p_xv   = p_bp  + 4 * N_BSD;
    float* p_xa   = p_xv  + N_BSD;
    float* p_ov   = p_xa  + N_BSD;        // ov/oa contiguous -> [2048][768]
    float* p_oa   = p_ov  + N_BSD;
    float* p_h    = p_oa  + N_BSD;        // [2048][512]

    const int nBlk = (int)(N_BSD / 256);

    cudaFuncSetAttribute(bilinear5_kernel,
                         cudaFuncAttributeMaxDynamicSharedMemorySize, BIL5_SMEM_BYTES);

    fuse_bias_kernel<<<1, 256>>>(mmfaB, p_bf);
    wconv_kernel<<<16384, 256>>>(bilW, p_Wh);
    float* p_b45 = p_bf;
    float* p_b67 = p_bf + 256;

    auto run_mmfa = [&](const float* xv, const float* xa,
                        const float* mv, const float* ma, float* o1, float* o2) {
        GB qk;
        qk.A[0] = xv;  qk.W[0] = mmfaW + 0 * 65536; qk.W2[0] = mmfaW + 2 * 65536;
        qk.b1[0] = mmfaB + 0 * 256; qk.b2[0] = mmfaB + 2 * 256; qk.E[0] = xv;  qk.C[0] = p_qkv;
        qk.A[1] = xa;  qk.W[1] = mmfaW + 1 * 65536; qk.W2[1] = mmfaW + 3 * 65536;
        qk.b1[1] = mmfaB + 1 * 256; qk.b2[1] = mmfaB + 3 * 256; qk.E[1] = xa;  qk.C[1] = p_qka;
        mma_gemm_kernel<<<dim3(512 / 64, M3 / 128, 2), 256>>>(qk, M3, 512, Dd, 256, 8, 0, 0);

        attn_kernel<<<Bn, 256>>>(xv, xa, p_qkv, p_qka, p_cat1, p_cat2);

        GB cc;
        cc.A[0] = p_cat1; cc.W[0] = mmfaW + 4 * 65536; cc.W2[0] = mmfaW + 5 * 65536;
        cc.b1[0] = p_b45; cc.b2[0] = p_b45; cc.E[0] = p_cat1; cc.C[0] = p_cva;
        cc.A[1] = p_cat2; cc.W[1] = mmfaW + 6 * 65536; cc.W2[1] = mmfaW + 7 * 65536;
        cc.b1[1] = p_b67; cc.b2[1] = p_b67; cc.E[1] = p_cat2; cc.C[1] = p_cav;
        mma_gemm_kernel<<<dim3(256 / 64, M3 / 128, 2), 256>>>(cc, M3, Dd, 512, 256, 4, 512, 256);

        bilinear5_kernel<<<dim3(24, 2, 4), 256, BIL5_SMEM_BYTES>>>(p_cva, p_cav, p_Wh, p_bp);
        bil_finish_kernel<<<nBlk, 256>>>(p_bp, xv, xa, t_c, mv, ma, o1, o2);
    };

    // encoders (vis||aud) fp32 SIMT (precision root)
    {
        GB32 e;
        e.A[0] = img;   e.W[0] = vis_W; e.b[0] = vis_b; e.C[0] = p_vis; e.K[0] = 4096;
        e.A[1] = audio; e.W[1] = aud_W; e.b[1] = aud_b; e.C[1] = p_aud; e.K[1] = 1024;
        gemm_kernel<<<dim3(16, 8, 2), 256>>>(e, Bn, 1024, 1);
    }

    // multi-scale -> tf32 RNA tensor path (z-batched, relu)
    {
        GB m;
        m.A[0] = p_vis; m.W[0] = m.W2[0] = msv_W; m.b1[0] = m.b2[0] = msv_b;
        m.E[0] = p_vis; m.C[0] = p_vms;
        m.A[1] = p_aud; m.W[1] = m.W2[1] = msa_W; m.b1[1] = m.b2[1] = msa_b;
        m.E[1] = p_aud; m.C[1] = p_ams;
        mma_gemm_kernel<<<dim3(SD / 64, Bn / 128, 2), 256>>>(m, Bn, SD, 1024, 1024, 1, 0, 0);
    }

    // MMfa 1: xv2 = M1*vms, xa2 = M1*ams ; MMfa 2: ov = M2*vms, oa = M2*ams
    run_mmfa(p_vms, p_ams, p_vms, p_ams, p_xv, p_xa);
    run_mmfa(p_xv, p_xa, p_vms, p_ams, p_ov, p_oa);

    float* out = (float*)d_out;
    float* fv = out;
    float* fa = out + (size_t)Bn * LAT;
    float* pv = fa + (size_t)Bn * LAT;
    float* pa = pv + (size_t)Bn * 10;

    // out_layer M-batched over (ov||oa) -> (fv||fa)
    {
        GB o1;
        o1.A[0] = o1.A[1] = p_ov; o1.W[0] = o1.W[1] = out_W1; o1.W2[0] = o1.W2[1] = out_W1;
        o1.b1[0] = o1.b1[1] = out_b1; o1.b2[0] = o1.b2[1] = out_b1;
        o1.E[0] = o1.E[1] = p_ov; o1.C[0] = o1.C[1] = p_h;
        mma_gemm_kernel<<<dim3(OUT1 / 64, 2 * Bn / 128, 1), 256>>>(o1, 2 * Bn, OUT1, SD, SD, 1, 0, 0);

        GB o2;
        o2.A[0] = o2.A[1] = p_h; o2.W[0] = o2.W[1] = out_W2; o2.W2[0] = o2.W2[1] = out_W2;
        o2.b1[0] = o2.b1[1] = out_b2; o2.b2[0] = o2.b2[1] = out_b2;
        o2.E[0] = o2.E[1] = p_h; o2.C[0] = o2.C[1] = fv;
        mma_gemm_kernel<<<dim3(LAT / 64, 2 * Bn / 128, 1), 256>>>(o2, 2 * Bn, LAT, OUT1, OUT1, 0, 0, 0);
    }

    cls_kernel<<<Bn / 8, 256>>>(fv, clsvW1, clsvW2, pv);
    cls_kernel<<<Bn / 8, 256>>>(fa, clsaW1, clsaW2, pa);
}

// round 12
// speedup vs baseline: 1.0130x; 1.0096x over previous
#include <cuda_runtime.h>
#include <cuda_fp16.h>
#include <math.h>
#include <stdint.h>

// ---------------- problem constants ----------------
static constexpr int Bn   = 1024;
static constexpr int M3   = 3072;   // B*S
static constexpr int Dd   = 256;
static constexpr int SD   = 768;
static constexpr int OUT1 = 512;
static constexpr int LAT  = 128;

static constexpr size_t N_BE  = (size_t)Bn * 1024;
static constexpr size_t N_BSD = (size_t)M3 * Dd;     // 786432

__device__ float g_scratch[2 * N_BE + 22 * N_BSD + (size_t)Bn * OUT1];
__device__ float g_bias_fused[512];            // [0:256)=b4+b5, [256:512)=b6+b7
__device__ __half g_Wh[16777216];              // bil_W in fp16 (32MB)

__device__ __forceinline__ float sigm(float x) { return 1.0f / (1.0f + expf(-x)); }

__device__ __forceinline__ unsigned tf32r(float x) {
    unsigned r;
    asm("cvt.rna.tf32.f32 %0, %1;" : "=r"(r) : "f"(x));
    return r;
}

__device__ __forceinline__ void mma_tf32(float& c0, float& c1, float& c2, float& c3,
                                         unsigned a0, unsigned a1, unsigned a2, unsigned a3,
                                         unsigned b0, unsigned b1) {
    asm("mma.sync.aligned.m16n8k8.row.col.f32.tf32.tf32.f32 "
        "{%0,%1,%2,%3}, {%4,%5,%6,%7}, {%8,%9}, {%0,%1,%2,%3};"
        : "+f"(c0), "+f"(c1), "+f"(c2), "+f"(c3)
        : "r"(a0), "r"(a1), "r"(a2), "r"(a3), "r"(b0), "r"(b1));
}

__device__ __forceinline__ void mma_f16(float& c0, float& c1, float& c2, float& c3,
                                        unsigned a0, unsigned a1, unsigned a2, unsigned a3,
                                        unsigned b0, unsigned b1) {
    asm("mma.sync.aligned.m16n8k16.row.col.f32.f16.f16.f32 "
        "{%0,%1,%2,%3}, {%4,%5,%6,%7}, {%8,%9}, {%0,%1,%2,%3};"
        : "+f"(c0), "+f"(c1), "+f"(c2), "+f"(c3)
        : "r"(a0), "r"(a1), "r"(a2), "r"(a3), "r"(b0), "r"(b1));
}

__device__ __forceinline__ void cpa16(void* smem_dst, const void* gsrc) {
    unsigned sa = (unsigned)__cvta_generic_to_shared(smem_dst);
    asm volatile("cp.async.cg.shared.global [%0], [%1], 16;" :: "r"(sa), "l"(gsrc));
}

// ---------------- helpers ----------------
__global__ void fuse_bias_kernel(const float* __restrict__ b, float* __restrict__ o)
{
    int i = threadIdx.x;
    o[i]       = b[4 * 256 + i] + b[5 * 256 + i];
    o[256 + i] = b[6 * 256 + i] + b[7 * 256 + i];
}

__global__ void wconv_kernel(const float* __restrict__ W, __half* __restrict__ Wh)
{
    size_t i = ((size_t)blockIdx.x * 256 + threadIdx.x) * 4;
    float4 v = *(const float4*)(W + i);
    *(__half2*)(Wh + i)     = __floats2half2_rn(v.x, v.y);
    *(__half2*)(Wh + i + 2) = __floats2half2_rn(v.z, v.w);
}

// ---------------- fp32 SIMT GEMM, z-batched (encoders) ----------
struct GB32 {
    const float* A[2]; const float* W[2]; const float* b[2]; float* C[2]; int K[2];
};

__global__ void __launch_bounds__(256) gemm_kernel(GB32 P, int M, int N, int flags)
{
    __shared__ __align__(16) float As[16][132];
    __shared__ __align__(16) float Ws[16][68];
    const int z = blockIdx.z;
    const float* A = P.A[z];
    const float* W = P.W[z];
    const float* bias = P.b[z];
    float* C = P.C[z];
    const int K = P.K[z];

    const int tid = threadIdx.x;
    const int tx = tid & 15, ty = tid >> 4;
    const int m0 = blockIdx.y * 128, n0 = blockIdx.x * 64;
    const int lrow = tid >> 2, lk = (tid & 3) << 2;

    const float* Ag0 = A + (size_t)(m0 + lrow) * K + lk;
    const float* Ag1 = A + (size_t)(m0 + lrow + 64) * K + lk;
    const float* Wg  = W + (size_t)(n0 + lrow) * K + lk;

    float acc[8][4] = {};
    for (int kt = 0; kt < K; kt += 16) {
        float4 a0 = *(const float4*)(Ag0 + kt);
        float4 a1 = *(const float4*)(Ag1 + kt);
        float4 w0 = *(const float4*)(Wg + kt);
        As[lk + 0][lrow] = a0.x; As[lk + 1][lrow] = a0.y;
        As[lk + 2][lrow] = a0.z; As[lk + 3][lrow] = a0.w;
        As[lk + 0][lrow + 64] = a1.x; As[lk + 1][lrow + 64] = a1.y;
        As[lk + 2][lrow + 64] = a1.z; As[lk + 3][lrow + 64] = a1.w;
        Ws[lk + 0][lrow] = w0.x; Ws[lk + 1][lrow] = w0.y;
        Ws[lk + 2][lrow] = w0.z; Ws[lk + 3][lrow] = w0.w;
        __syncthreads();
#pragma unroll
        for (int k = 0; k < 16; k++) {
            float ar[8];
            *(float4*)&ar[0] = *(const float4*)&As[k][ty * 8];
            *(float4*)&ar[4] = *(const float4*)&As[k][ty * 8 + 4];
            float4 b = *(const float4*)&Ws[k][tx * 4];
#pragma unroll
            for (int i = 0; i < 8; i++) {
                acc[i][0] = fmaf(ar[i], b.x, acc[i][0]);
                acc[i][1] = fmaf(ar[i], b.y, acc[i][1]);
                acc[i][2] = fmaf(ar[i], b.z, acc[i][2]);
                acc[i][3] = fmaf(ar[i], b.w, acc[i][3]);
            }
        }
        __syncthreads();
    }
#pragma unroll
    for (int i = 0; i < 8; i++) {
        int row = m0 + ty * 8 + i;
#pragma unroll
        for (int j = 0; j < 4; j++) {
            int col = n0 + tx * 4 + j;
            float v = acc[i][j] + bias[col];
            if (flags & 1) v = fmaxf(v, 0.0f);
            C[(size_t)row * N + col] = v;
        }
    }
}

// ---------------- tf32 tensor GEMM v3: 3-stage cp.async pipeline + explicit RNA -------
// flags: bit0 relu ; bit2 sigmul: out = sigm(v * E[row*eld + eoff + col]) ; bit3 N-split
struct GB {
    const float* A[2]; const float* W[2]; const float* W2[2];
    const float* b1[2]; const float* b2[2]; const float* E[2]; float* C[2];
};

__global__ void __launch_bounds__(256) mma_gemm_kernel(
    GB P, int M, int N, int K, int Kx, int flags, int eld, int eoff)
{
    __shared__ __align__(16) float As[3][128][20];   // 30720 B
    __shared__ __align__(16) float Ws[3][64][20];    // 15360 B
    const int z = blockIdx.z;
    const float* A = P.A[z];
    const float* W = P.W[z];
    const float* W2 = P.W2[z];
    const float* bias = P.b1[z];
    const float* bias2 = P.b2[z];
    const float* E = P.E[z];
    float* C = P.C[z];

    const int tid = threadIdx.x;
    const int lane = tid & 31, wid = tid >> 5;
    const int wm = wid >> 1, wn = wid & 1;     // 4m x 2n
    const int m0 = blockIdx.y * 128, n0 = blockIdx.x * 64;
    const int c4 = lane & 3, lr = lane >> 2;
    const int Kb = K - Kx;
    const bool nsplit = (flags & 8) != 0;

    float c[2][4][4];
#pragma unroll
    for (int mt = 0; mt < 2; mt++)
#pragma unroll
        for (int nt = 0; nt < 4; nt++)
#pragma unroll
            for (int e = 0; e < 4; e++) c[mt][nt][e] = 0.0f;

    const int arow0 = tid >> 2, ach = tid & 3;
    auto issue_tile = [&](int kt) {
        int buf = kt % 3;
        int kbase = kt * 16;
#pragma unroll
        for (int u = 0; u < 2; u++) {
            int chunk = tid + 256 * u;
            int row = chunk >> 2, ch = chunk & 3;
            cpa16(&As[buf][row][ch * 4], A + (size_t)(m0 + row) * K + kbase + ch * 4);
        }
        {
            int row = arow0, ch = ach;
            int k = kbase + ch * 4;
            const float* ws;
            if (nsplit) {
                int n = n0 + row;
                ws = (n < Kx) ? (W + (size_t)n * K + k) : (W2 + (size_t)(n - Kx) * K + k);
            } else {
                ws = (k < Kx) ? (W + (size_t)(n0 + row) * Kx + k)
                              : (W2 + (size_t)(n0 + row) * Kb + (k - Kx));
            }
            cpa16(&Ws[buf][row][ch * 4], ws);
        }
        asm volatile("cp.async.commit_group;");
    };

    const int ktiles = K >> 4;
    issue_tile(0);
    if (ktiles > 1) issue_tile(1);

    const int rbB = wm * 32 + lr;
    for (int kt = 0; kt < ktiles; kt++) {
        if (kt + 1 < ktiles) asm volatile("cp.async.wait_group 1;" ::: "memory");
        else                 asm volatile("cp.async.wait_group 0;" ::: "memory");
        __syncthreads();   // tile kt visible; compute(kt-1) done everywhere
        if (kt + 2 < ktiles) issue_tile(kt + 2);
        const int buf = kt % 3;
#pragma unroll
        for (int kk = 0; kk < 16; kk += 8) {
            unsigned a[2][4];
#pragma unroll
            for (int mt = 0; mt < 2; mt++) {
                int rb = rbB + mt * 16;
                a[mt][0] = tf32r(As[buf][rb][kk + c4]);
                a[mt][1] = tf32r(As[buf][rb + 8][kk + c4]);
                a[mt][2] = tf32r(As[buf][rb][kk + c4 + 4]);
                a[mt][3] = tf32r(As[buf][rb + 8][kk + c4 + 4]);
            }
#pragma unroll
            for (int nt = 0; nt < 4; nt++) {
                int nb = wn * 32 + nt * 8 + lr;
                unsigned b0 = tf32r(Ws[buf][nb][kk + c4]);
                unsigned b1 = tf32r(Ws[buf][nb][kk + c4 + 4]);
#pragma unroll
                for (int mt = 0; mt < 2; mt++)
                    mma_tf32(c[mt][nt][0], c[mt][nt][1], c[mt][nt][2], c[mt][nt][3],
                             a[mt][0], a[mt][1], a[mt][2], a[mt][3], b0, b1);
            }
        }
        // no trailing sync — next iter's sync gates buffer reuse (3-deep ring is safe:
        // buffer (kt+2)%3 was consumed in iteration kt-1, before this iteration's sync)
    }

#pragma unroll
    for (int mt = 0; mt < 2; mt++) {
#pragma unroll
        for (int nt = 0; nt < 4; nt++) {
            int row = m0 + wm * 32 + mt * 16 + lr;
            int col = n0 + wn * 32 + nt * 8 + c4 * 2;
#pragma unroll
            for (int e = 0; e < 4; e++) {
                int rr = row + (e >> 1) * 8;
                int cc = col + (e & 1);
                float bv = nsplit ? ((cc < Kx) ? bias[cc] : bias2[cc - Kx]) : bias[cc];
                float v = c[mt][nt][e] + bv;
                if (flags & 1) v = fmaxf(v, 0.0f);
                if (flags & 4) v = sigm(v * E[(size_t)rr * eld + eoff + cc]);
                C[(size_t)rr * N + cc] = v;
            }
        }
    }
}

// ---------------- fp16 bilinear v5 (round-10 passing version, unchanged) ----------
static constexpr int BIL5_SMEM_BYTES = (128 * 264 + 2 * 128 * 72) * 2;

__global__ void __launch_bounds__(256) bilinear5_kernel(
    const float* __restrict__ cva, const float* __restrict__ cav,
    const __half* __restrict__ Wh, float* __restrict__ part)
{
    extern __shared__ __half sh[];
    __half* s_cav = sh;                // [128][264]
    __half* s_W   = sh + 128 * 264;    // [2][128][72]

    const int tid = threadIdx.x;
    const int lane = tid & 31, wid = tid >> 5;
    const int wm = wid & 1, wn = wid >> 1;   // 2m(64) x 4n(32)
    const int g = lane >> 2, q = lane & 3;
    const int r0 = blockIdx.x * 128, o0 = blockIdx.y * 128;
    const int iBase = blockIdx.z * 64;

    for (int f = tid; f < 8192; f += 256) {
        int row = f >> 6, q4 = f & 63;
        float4 w = *(const float4*)(cav + (size_t)(r0 + row) * 256 + q4 * 4);
        __half* d = s_cav + row * 264 + q4 * 4;
        *(__half2*)(d)     = __floats2half2_rn(w.x, w.y);
        *(__half2*)(d + 2) = __floats2half2_rn(w.z, w.w);
    }

    float c[4][4][4];
#pragma unroll
    for (int mt = 0; mt < 4; mt++)
#pragma unroll
        for (int nt = 0; nt < 4; nt++)
#pragma unroll
            for (int e = 0; e < 4; e++) c[mt][nt][e] = 0.0f;

    auto issue_tile = [&](int it) {
        int i = iBase + (it >> 2), h = it & 3;
        __half* dst0 = s_W + (it & 1) * 128 * 72;
#pragma unroll
        for (int u = 0; u < 4; u++) {
            int cidx = tid + 256 * u;          // 0..1023
            int o = cidx >> 3, ch = cidx & 7;
            const __half* src = Wh + (size_t)(o0 + o) * 65536 + (size_t)i * 256 + h * 64 + ch * 8;
            cpa16(dst0 + o * 72 + ch * 8, src);
        }
        asm volatile("cp.async.commit_group;");
    };

    issue_tile(0);

    const int rb = wm * 64 + g;
    const float* cvaB = cva + (size_t)r0 * 256;

    for (int it = 0; it < 256; it++) {
        asm volatile("cp.async.wait_group 0;");
        __syncthreads();
        if (it + 1 < 256) issue_tile(it + 1);

        const __half* wbuf = s_W + (it & 1) * 128 * 72;
        const int ig = iBase + (it >> 2);
        const int h = it & 3;
        __half2 s[8];
#pragma unroll
        for (int mt = 0; mt < 4; mt++) {
            s[2 * mt]     = __half2half2(__float2half_rn(cvaB[(size_t)(rb + mt * 16) * 256 + ig]));
            s[2 * mt + 1] = __half2half2(__float2half_rn(cvaB[(size_t)(rb + mt * 16 + 8) * 256 + ig]));
        }

#pragma unroll
        for (int jc = 0; jc < 4; jc++) {
            const int jlo = h * 64 + jc * 16 + 2 * q;
            const int jhi = jlo + 8;
            __half2 a[4][4];
#pragma unroll
            for (int mt = 0; mt < 4; mt++) {
                int r1 = rb + mt * 16, r2 = r1 + 8;
                a[mt][0] = __hmul2(*(__half2*)&s_cav[r1 * 264 + jlo], s[2 * mt]);
                a[mt][1] = __hmul2(*(__half2*)&s_cav[r2 * 264 + jlo], s[2 * mt + 1]);
                a[mt][2] = __hmul2(*(__half2*)&s_cav[r1 * 264 + jhi], s[2 * mt]);
                a[mt][3] = __hmul2(*(__half2*)&s_cav[r2 * 264 + jhi], s[2 * mt + 1]);
            }
            const int kloc = jc * 16;
#pragma unroll
            for (int nt = 0; nt < 4; nt++) {
                int oc = wn * 32 + nt * 8 + g;
                unsigned b0 = *(const unsigned*)&wbuf[oc * 72 + kloc + 2 * q];
                unsigned b1 = *(const unsigned*)&wbuf[oc * 72 + kloc + 2 * q + 8];
#pragma unroll
                for (int mt = 0; mt < 4; mt++)
                    mma_f16(c[mt][nt][0], c[mt][nt][1], c[mt][nt][2], c[mt][nt][3],
                            *(unsigned*)&a[mt][0], *(unsigned*)&a[mt][1],
                            *(unsigned*)&a[mt][2], *(unsigned*)&a[mt][3], b0, b1);
            }
        }
    }

    float* P = part + (size_t)blockIdx.z * N_BSD;
#pragma unroll
    for (int mt = 0; mt < 4; mt++) {
#pragma unroll
        for (int nt = 0; nt < 4; nt++) {
            int row = r0 + wm * 64 + mt * 16 + g;
            int col = o0 + wn * 32 + nt * 8 + q * 2;
            float* d0 = P + (size_t)row * 256 + col;
            float* d1 = P + (size_t)(row + 8) * 256 + col;
            d0[0] = c[mt][nt][0]; d0[1] = c[mt][nt][1];
            d1[0] = c[mt][nt][2]; d1[1] = c[mt][nt][3];
        }
    }
}

// finish: j = sigm(sum partials); m = tc*j*xv + (1-j)*xa; o1 = m*mv; o2 = m*ma
__global__ void bil_finish_kernel(const float* __restrict__ part,
                                  const float* __restrict__ xv, const float* __restrict__ xa,
                                  const float* __restrict__ tcp,
                                  const float* __restrict__ mv, const float* __restrict__ ma,
                                  float* __restrict__ o1, float* __restrict__ o2)
{
    int i = blockIdx.x * 256 + threadIdx.x;
    float s = part[i] + part[i + N_BSD] + part[i + 2 * N_BSD] + part[i + 3 * N_BSD];
    float j = sigm(s);
    float m = (*tcp) * j * xv[i] + (1.0f - j) * xa[i];
    o1[i] = m * mv[i];
    o2[i] = m * ma[i];
}

// ---------------- attention ----------------
__global__ void __launch_bounds__(256) attn_kernel(
    const float* __restrict__ xv, const float* __restrict__ xa,
    const float* __restrict__ qkv_v, const float* __restrict__ qkv_a,
    float* __restrict__ cat1, float* __restrict__ cat2)
{
    __shared__ float s_x[2][3][256];
    __shared__ float s_q[2][3][256];
    __shared__ float s_k[2][3][256];
    __shared__ float s_sc[4][3][3];
    const int tid = threadIdx.x;
    const size_t base = (size_t)blockIdx.x * 768;
    const size_t base2 = (size_t)blockIdx.x * 1536;
    const size_t qbase = (size_t)blockIdx.x * 3 * 512;

    float* fx = &s_x[0][0][0];
    float* fq = &s_q[0][0][0];
    float* fk = &s_k[0][0][0];
    for (int idx = tid; idx < 768; idx += 256) {
        int s3 = idx >> 8, d = idx & 255;
        size_t qoff = qbase + (size_t)s3 * 512 + d;
        fx[idx] = xv[base + idx]; fx[768 + idx] = xa[base + idx];
        fq[idx] = qkv_v[qoff];        fq[768 + idx] = qkv_a[qoff];
        fk[idx] = qkv_v[qoff + 256];  fk[768 + idx] = qkv_a[qoff + 256];
    }
    __syncthreads();

    const int w = tid >> 5, lane = tid & 31;
    for (int task = w; task < 36; task += 8) {
        int type = task / 9, rem = task % 9, s3 = rem / 3, t3 = rem % 3;
        int qsel = type >> 1;
        int ksel = (type == 0 || type == 3) ? 1 : 0;
        float sum = 0.0f;
        for (int d = lane; d < 256; d += 32) sum += s_q[qsel][s3][d] * s_k[ksel][t3][d];
#pragma unroll
        for (int off = 16; off; off >>= 1) sum += __shfl_down_sync(0xffffffffu, sum, off);
        if (lane == 0) s_sc[type][s3][t3] = sum;
    }
    __syncthreads();

    if (tid < 12) {
        int type = tid / 3, s3 = tid % 3;
        float a = s_sc[type][s3][0], b = s_sc[type][s3][1], c = s_sc[type][s3][2];
        float m = fmaxf(a, fmaxf(b, c));
        float ea = expf(a - m), eb = expf(b - m), ec = expf(c - m);
        float inv = 0.0625f / (ea + eb + ec);
        s_sc[type][s3][0] = ea * inv; s_sc[type][s3][1] = eb * inv; s_sc[type][s3][2] = ec * inv;
    }
    __syncthreads();

    for (int idx = tid; idx < 3072; idx += 256) {
        int type = idx / 768, rem = idx % 768;
        int s3 = rem >> 8, d = rem & 255;
        int xsel = (type == 0 || type == 3) ? 1 : 0;
        float v = s_sc[type][s3][0] * s_x[xsel][0][d]
                + s_sc[type][s3][1] * s_x[xsel][1][d]
                + s_sc[type][s3][2] * s_x[xsel][2][d];
        float* dst = (type < 2) ? cat1 : cat2;
        dst[base2 + (size_t)s3 * 512 + ((type & 1) ? 256 : 0) + d] = v;
    }
}

// ---------------- classifier ----------------
__global__ void __launch_bounds__(256) cls_kernel(
    const float* __restrict__ F, const float* __restrict__ W1,
    const float* __restrict__ W2, float* __restrict__ P)
{
    __shared__ float s_f[8][128];
    __shared__ float s_w1[32][129];
    __shared__ float s_w2[320];
    __shared__ float s_h[8][32];
    const int tid = threadIdx.x;
    const int r0 = blockIdx.x * 8;
    for (int idx = tid; idx < 1024; idx += 256) s_f[idx >> 7][idx & 127] = F[(size_t)r0 * 128 + idx];
    for (int idx = tid; idx < 4096; idx += 256) s_w1[idx >> 7][idx & 127] = W1[idx];
    for (int idx = tid; idx < 320; idx += 256) s_w2[idx] = W2[idx];
    __syncthreads();
    const int w = tid >> 5, lane = tid & 31;
    float h = 0.0f;
#pragma unroll 8
    for (int d = 0; d < 128; d++) h = fmaf(s_f[w][d], s_w1[lane][d], h);
    s_h[w][lane] = fmaxf(h, 0.0f);
    __syncwarp();
    if (lane < 10) {
        float p = 0.0f;
#pragma unroll
        for (int k = 0; k < 32; k++) p = fmaf(s_h[w][k], s_w2[lane * 32 + k], p);
        P[(size_t)(r0 + w) * 10 + lane] = p;
    }
}

// ---------------- host ----------------
extern "C" void kernel_launch(void* const* d_in, const int* in_sizes, int n_in,
                              void* d_out, int out_size)
{
    const float* img    = (const float*)d_in[0];
    const float* audio  = (const float*)d_in[1];
    const float* vis_W  = (const float*)d_in[2];
    const float* vis_b  = (const float*)d_in[3];
    const float* aud_W  = (const float*)d_in[4];
    const float* aud_b  = (const float*)d_in[5];
    const float* msv_W  = (const float*)d_in[6];
    const float* msv_b  = (const float*)d_in[7];
    const float* msa_W  = (const float*)d_in[8];
    const float* msa_b  = (const float*)d_in[9];
    const float* mmfaW  = (const float*)d_in[10];
    const float* mmfaB  = (const float*)d_in[11];
    const float* bilW   = (const float*)d_in[12];
    const float* t_c    = (const float*)d_in[13];
    const float* out_W1 = (const float*)d_in[14];
    const float* out_b1 = (const float*)d_in[15];
    const float* out_W2 = (const float*)d_in[16];
    const float* out_b2 = (const float*)d_in[17];
    const float* clsvW1 = (const float*)d_in[18];
    const float* clsvW2 = (const float*)d_in[19];
    const float* clsaW1 = (const float*)d_in[20];
    const float* clsaW2 = (const float*)d_in[21];

    float* S = nullptr;
    cudaGetSymbolAddress((void**)&S, g_scratch);
    float* p_bf = nullptr;
    cudaGetSymbolAddress((void**)&p_bf, g_bias_fused);
    __half* p_Wh = nullptr;
    cudaGetSymbolAddress((void**)&p_Wh, g_Wh);

    float* p_vis  = S;
    float* p_aud  = p_vis + N_BE;
    float* p_vms  = p_aud + N_BE;
    float* p_ams  = p_vms + N_BSD;
    float* p_qkv  = p_ams + N_BSD;        // [3072][512]
    float* p_qka  = p_qkv + 2 * N_BSD;    // [3072][512]
    float* p_cat1 = p_qka + 2 * N_BSD;    // [3072][512]
    float* p_cat2 = p_cat1 + 2 * N_BSD;   // [3072][512]
    float* p_cva  = p_cat2 + 2 * N_BSD;
    float* p_cav  = p_cva + N_BSD;
    float* p_bp   = p_cav + N_BSD;        // 4 x [3072][256]
    float* p_xv   = p_bp  + 4 * N_BSD;
    float* p_xa   = p_xv  + N_BSD;
    float* p_ov   = p_xa  + N_BSD;        // ov/oa contiguous -> [2048][768]
    float* p_oa   = p_ov  + N_BSD;
    float* p_h    = p_oa  + N_BSD;        // [2048][512]

    const int nBlk = (int)(N_BSD / 256);

    cudaFuncSetAttribute(bilinear5_kernel,
                         cudaFuncAttributeMaxDynamicSharedMemorySize, BIL5_SMEM_BYTES);

    fuse_bias_kernel<<<1, 256>>>(mmfaB, p_bf);
    wconv_kernel<<<16384, 256>>>(bilW, p_Wh);
    float* p_b45 = p_bf;
    float* p_b67 = p_bf + 256;

    auto run_mmfa = [&](const float* xv, const float* xa,
                        const float* mv, const float* ma, float* o1, float* o2) {
        GB qk;
        qk.A[0] = xv;  qk.W[0] = mmfaW + 0 * 65536; qk.W2[0] = mmfaW + 2 * 65536;
        qk.b1[0] = mmfaB + 0 * 256; qk.b2[0] = mmfaB + 2 * 256; qk.E[0] = xv;  qk.C[0] = p_qkv;
        qk.A[1] = xa;  qk.W[1] = mmfaW + 1 * 65536; qk.W2[1] = mmfaW + 3 * 65536;
        qk.b1[1] = mmfaB + 1 * 256; qk.b2[1] = mmfaB + 3 * 256; qk.E[1] = xa;  qk.C[1] = p_qka;
        mma_gemm_kernel<<<dim3(512 / 64, M3 / 128, 2), 256>>>(qk, M3, 512, Dd, 256, 8, 0, 0);

        attn_kernel<<<Bn, 256>>>(xv, xa, p_qkv, p_qka, p_cat1, p_cat2);

        GB cc;
        cc.A[0] = p_cat1; cc.W[0] = mmfaW + 4 * 65536; cc.W2[0] = mmfaW + 5 * 65536;
        cc.b1[0] = p_b45; cc.b2[0] = p_b45; cc.E[0] = p_cat1; cc.C[0] = p_cva;
        cc.A[1] = p_cat2; cc.W[1] = mmfaW + 6 * 65536; cc.W2[1] = mmfaW + 7 * 65536;
        cc.b1[1] = p_b67; cc.b2[1] = p_b67; cc.E[1] = p_cat2; cc.C[1] = p_cav;
        mma_gemm_kernel<<<dim3(256 / 64, M3 / 128, 2), 256>>>(cc, M3, Dd, 512, 256, 4, 512, 256);

        bilinear5_kernel<<<dim3(24, 2, 4), 256, BIL5_SMEM_BYTES>>>(p_cva, p_cav, p_Wh, p_bp);
        bil_finish_kernel<<<nBlk, 256>>>(p_bp, xv, xa, t_c, mv, ma, o1, o2);
    };

    // encoders (vis||aud) fp32 SIMT (precision root)
    {
        GB32 e;
        e.A[0] = img;   e.W[0] = vis_W; e.b[0] = vis_b; e.C[0] = p_vis; e.K[0] = 4096;
        e.A[1] = audio; e.W[1] = aud_W; e.b[1] = aud_b; e.C[1] = p_aud; e.K[1] = 1024;
        gemm_kernel<<<dim3(16, 8, 2), 256>>>(e, Bn, 1024, 1);
    }

    // multi-scale -> tf32 RNA tensor path (z-batched, relu)
    {
        GB m;
        m.A[0] = p_vis; m.W[0] = m.W2[0] = msv_W; m.b1[0] = m.b2[0] = msv_b;
        m.E[0] = p_vis; m.C[0] = p_vms;
        m.A[1] = p_aud; m.W[1] = m.W2[1] = msa_W; m.b1[1] = m.b2[1] = msa_b;
        m.E[1] = p_aud; m.C[1] = p_ams;
        mma_gemm_kernel<<<dim3(SD / 64, Bn / 128, 2), 256>>>(m, Bn, SD, 1024, 1024, 1, 0, 0);
    }

    // MMfa 1: xv2 = M1*vms, xa2 = M1*ams ; MMfa 2: ov = M2*vms, oa = M2*ams
    run_mmfa(p_vms, p_ams, p_vms, p_ams, p_xv, p_xa);
    run_mmfa(p_xv, p_xa, p_vms, p_ams, p_ov, p_oa);

    float* out = (float*)d_out;
    float* fv = out;
    float* fa = out + (size_t)Bn * LAT;
    float* pv = fa + (size_t)Bn * LAT;
    float* pa = pv + (size_t)Bn * 10;

    // out_layer M-batched over (ov||oa) -> (fv||fa)
    {
        GB o1;
        o1.A[0] = o1.A[1] = p_ov; o1.W[0] = o1.W[1] = out_W1; o1.W2[0] = o1.W2[1] = out_W1;
        o1.b1[0] = o1.b1[1] = out_b1; o1.b2[0] = o1.b2[1] = out_b1;
        o1.E[0] = o1.E[1] = p_ov; o1.C[0] = o1.C[1] = p_h;
        mma_gemm_kernel<<<dim3(OUT1 / 64, 2 * Bn / 128, 1), 256>>>(o1, 2 * Bn, OUT1, SD, SD, 1, 0, 0);

        GB o2;
        o2.A[0] = o2.A[1] = p_h; o2.W[0] = o2.W[1] = out_W2; o2.W2[0] = o2.W2[1] = out_W2;
        o2.b1[0] = o2.b1[1] = out_b2; o2.b2[0] = o2.b2[1] = out_b2;
        o2.E[0] = o2.E[1] = p_h; o2.C[0] = o2.C[1] = fv;
        mma_gemm_kernel<<<dim3(LAT / 64, 2 * Bn / 128, 1), 256>>>(o2, 2 * Bn, LAT, OUT1, OUT1, 0, 0, 0);
    }

    cls_kernel<<<Bn / 8, 256>>>(fv, clsvW1, clsvW2, pv);
    cls_kernel<<<Bn / 8, 256>>>(fa, clsaW1, clsaW2, pa);
}

// round 13
// speedup vs baseline: 1.1243x; 1.1099x over previous
#include <cuda_runtime.h>
#include <cuda_fp16.h>
#include <math.h>
#include <stdint.h>

// ---------------- problem constants ----------------
static constexpr int Bn   = 1024;
static constexpr int M3   = 3072;   // B*S
static constexpr int Dd   = 256;
static constexpr int SD   = 768;
static constexpr int OUT1 = 512;
static constexpr int LAT  = 128;

static constexpr size_t N_BE  = (size_t)Bn * 1024;
static constexpr size_t N_BSD = (size_t)M3 * Dd;     // 786432

__device__ float g_scratch[2 * N_BE + 26 * N_BSD + (size_t)Bn * OUT1];
__device__ float g_bias_fused[512];            // [0:256)=b4+b5, [256:512)=b6+b7
__device__ __half g_Wh[16777216];              // bil_W in fp16 (32MB)

__device__ __forceinline__ float sigm(float x) { return 1.0f / (1.0f + expf(-x)); }

__device__ __forceinline__ unsigned tf32r(float x) {
    unsigned r;
    asm("cvt.rna.tf32.f32 %0, %1;" : "=r"(r) : "f"(x));
    return r;
}

__device__ __forceinline__ void mma_tf32(float& c0, float& c1, float& c2, float& c3,
                                         unsigned a0, unsigned a1, unsigned a2, unsigned a3,
                                         unsigned b0, unsigned b1) {
    asm("mma.sync.aligned.m16n8k8.row.col.f32.tf32.tf32.f32 "
        "{%0,%1,%2,%3}, {%4,%5,%6,%7}, {%8,%9}, {%0,%1,%2,%3};"
        : "+f"(c0), "+f"(c1), "+f"(c2), "+f"(c3)
        : "r"(a0), "r"(a1), "r"(a2), "r"(a3), "r"(b0), "r"(b1));
}

__device__ __forceinline__ void mma_f16(float& c0, float& c1, float& c2, float& c3,
                                        unsigned a0, unsigned a1, unsigned a2, unsigned a3,
                                        unsigned b0, unsigned b1) {
    asm("mma.sync.aligned.m16n8k16.row.col.f32.f16.f16.f32 "
        "{%0,%1,%2,%3}, {%4,%5,%6,%7}, {%8,%9}, {%0,%1,%2,%3};"
        : "+f"(c0), "+f"(c1), "+f"(c2), "+f"(c3)
        : "r"(a0), "r"(a1), "r"(a2), "r"(a3), "r"(b0), "r"(b1));
}

__device__ __forceinline__ void cpa16(void* smem_dst, const void* gsrc) {
    unsigned sa = (unsigned)__cvta_generic_to_shared(smem_dst);
    asm volatile("cp.async.cg.shared.global [%0], [%1], 16;" :: "r"(sa), "l"(gsrc));
}

// ---------------- helpers ----------------
__global__ void fuse_bias_kernel(const float* __restrict__ b, float* __restrict__ o)
{
    int i = threadIdx.x;
    o[i]       = b[4 * 256 + i] + b[5 * 256 + i];
    o[256 + i] = b[6 * 256 + i] + b[7 * 256 + i];
}

__global__ void wconv_kernel(const float* __restrict__ W, __half* __restrict__ Wh)
{
    size_t i = ((size_t)blockIdx.x * 256 + threadIdx.x) * 4;
    float4 v = *(const float4*)(W + i);
    *(__half2*)(Wh + i)     = __floats2half2_rn(v.x, v.y);
    *(__half2*)(Wh + i + 2) = __floats2half2_rn(v.z, v.w);
}

// copy with RNA-tf32 rounding (weights for tf32 GEMMs): in-MMA RZ becomes identity
__global__ void wround_kernel(const float* __restrict__ src, float* __restrict__ dst)
{
    size_t i = ((size_t)blockIdx.x * 256 + threadIdx.x) * 4;
    float4 v = *(const float4*)(src + i);
    float4 o;
    o.x = __uint_as_float(tf32r(v.x));
    o.y = __uint_as_float(tf32r(v.y));
    o.z = __uint_as_float(tf32r(v.z));
    o.w = __uint_as_float(tf32r(v.w));
    *(float4*)(dst + i) = o;
}

// ---------------- fp32 SIMT GEMM, z-batched (encoders), register-prefetch --------
struct GB32 {
    const float* A[2]; const float* W[2]; const float* b[2]; float* C[2]; int K[2];
};

__global__ void __launch_bounds__(256) gemm_kernel(GB32 P, int M, int N, int flags)
{
    __shared__ __align__(16) float As[16][132];
    __shared__ __align__(16) float Ws[16][68];
    const int z = blockIdx.z;
    const float* A = P.A[z];
    const float* W = P.W[z];
    const float* bias = P.b[z];
    float* C = P.C[z];
    const int K = P.K[z];

    const int tid = threadIdx.x;
    const int tx = tid & 15, ty = tid >> 4;
    const int m0 = blockIdx.y * 128, n0 = blockIdx.x * 64;
    const int lrow = tid >> 2, lk = (tid & 3) << 2;

    const float* Ag0 = A + (size_t)(m0 + lrow) * K + lk;
    const float* Ag1 = A + (size_t)(m0 + lrow + 64) * K + lk;
    const float* Wg  = W + (size_t)(n0 + lrow) * K + lk;

    float4 a0 = *(const float4*)(Ag0);
    float4 a1 = *(const float4*)(Ag1);
    float4 w0 = *(const float4*)(Wg);

    float acc[8][4] = {};
    for (int kt = 0; kt < K; kt += 16) {
        As[lk + 0][lrow] = a0.x; As[lk + 1][lrow] = a0.y;
        As[lk + 2][lrow] = a0.z; As[lk + 3][lrow] = a0.w;
        As[lk + 0][lrow + 64] = a1.x; As[lk + 1][lrow + 64] = a1.y;
        As[lk + 2][lrow + 64] = a1.z; As[lk + 3][lrow + 64] = a1.w;
        Ws[lk + 0][lrow] = w0.x; Ws[lk + 1][lrow] = w0.y;
        Ws[lk + 2][lrow] = w0.z; Ws[lk + 3][lrow] = w0.w;
        __syncthreads();
        if (kt + 16 < K) {
            a0 = *(const float4*)(Ag0 + kt + 16);
            a1 = *(const float4*)(Ag1 + kt + 16);
            w0 = *(const float4*)(Wg + kt + 16);
        }
#pragma unroll
        for (int k = 0; k < 16; k++) {
            float ar[8];
            *(float4*)&ar[0] = *(const float4*)&As[k][ty * 8];
            *(float4*)&ar[4] = *(const float4*)&As[k][ty * 8 + 4];
            float4 b = *(const float4*)&Ws[k][tx * 4];
#pragma unroll
            for (int i = 0; i < 8; i++) {
                acc[i][0] = fmaf(ar[i], b.x, acc[i][0]);
                acc[i][1] = fmaf(ar[i], b.y, acc[i][1]);
                acc[i][2] = fmaf(ar[i], b.z, acc[i][2]);
                acc[i][3] = fmaf(ar[i], b.w, acc[i][3]);
            }
        }
        __syncthreads();
    }
#pragma unroll
    for (int i = 0; i < 8; i++) {
        int row = m0 + ty * 8 + i;
#pragma unroll
        for (int j = 0; j < 4; j++) {
            int col = n0 + tx * 4 + j;
            float v = acc[i][j] + bias[col];
            if (flags & 1) v = fmaxf(v, 0.0f);
            C[(size_t)row * N + col] = v;
        }
    }
}

// ---------------- tf32 tensor GEMM v4: 3-stage cp.async; weights pre-rounded -------
// flags: bit0 relu ; bit2 sigmul ; bit3 N-split ; bit4 A pre-rounded (skip a-cvt) ;
//        bit5 round output to tf32 at store
struct GB {
    const float* A[2]; const float* W[2]; const float* W2[2];
    const float* b1[2]; const float* b2[2]; const float* E[2]; float* C[2];
};

__global__ void __launch_bounds__(256) mma_gemm_kernel(
    GB P, int M, int N, int K, int Kx, int flags, int eld, int eoff)
{
    __shared__ __align__(16) float As[3][128][20];
    __shared__ __align__(16) float Ws[3][64][20];
    const int z = blockIdx.z;
    const float* A = P.A[z];
    const float* W = P.W[z];
    const float* W2 = P.W2[z];
    const float* bias = P.b1[z];
    const float* bias2 = P.b2[z];
    const float* E = P.E[z];
    float* C = P.C[z];

    const int tid = threadIdx.x;
    const int lane = tid & 31, wid = tid >> 5;
    const int wm = wid >> 1, wn = wid & 1;
    const int m0 = blockIdx.y * 128, n0 = blockIdx.x * 64;
    const int c4 = lane & 3, lr = lane >> 2;
    const int Kb = K - Kx;
    const bool nsplit = (flags & 8) != 0;
    const bool a_ready = (flags & 16) != 0;

    float c[2][4][4];
#pragma unroll
    for (int mt = 0; mt < 2; mt++)
#pragma unroll
        for (int nt = 0; nt < 4; nt++)
#pragma unroll
            for (int e = 0; e < 4; e++) c[mt][nt][e] = 0.0f;

    const int arow0 = tid >> 2, ach = tid & 3;
    auto issue_tile = [&](int kt) {
        int buf = kt % 3;
        int kbase = kt * 16;
#pragma unroll
        for (int u = 0; u < 2; u++) {
            int chunk = tid + 256 * u;
            int row = chunk >> 2, ch = chunk & 3;
            cpa16(&As[buf][row][ch * 4], A + (size_t)(m0 + row) * K + kbase + ch * 4);
        }
        {
            int row = arow0, ch = ach;
            int k = kbase + ch * 4;
            const float* ws;
            if (nsplit) {
                int n = n0 + row;
                ws = (n < Kx) ? (W + (size_t)n * K + k) : (W2 + (size_t)(n - Kx) * K + k);
            } else {
                ws = (k < Kx) ? (W + (size_t)(n0 + row) * Kx + k)
                              : (W2 + (size_t)(n0 + row) * Kb + (k - Kx));
            }
            cpa16(&Ws[buf][row][ch * 4], ws);
        }
        asm volatile("cp.async.commit_group;");
    };

    const int ktiles = K >> 4;
    issue_tile(0);
    if (ktiles > 1) issue_tile(1);

    const int rbB = wm * 32 + lr;
    for (int kt = 0; kt < ktiles; kt++) {
        if (kt + 1 < ktiles) asm volatile("cp.async.wait_group 1;" ::: "memory");
        else                 asm volatile("cp.async.wait_group 0;" ::: "memory");
        __syncthreads();
        if (kt + 2 < ktiles) issue_tile(kt + 2);
        const int buf = kt % 3;
#pragma unroll
        for (int kk = 0; kk < 16; kk += 8) {
            unsigned a[2][4];
#pragma unroll
            for (int mt = 0; mt < 2; mt++) {
                int rb = rbB + mt * 16;
                if (a_ready) {
                    a[mt][0] = __float_as_uint(As[buf][rb][kk + c4]);
                    a[mt][1] = __float_as_uint(As[buf][rb + 8][kk + c4]);
                    a[mt][2] = __float_as_uint(As[buf][rb][kk + c4 + 4]);
                    a[mt][3] = __float_as_uint(As[buf][rb + 8][kk + c4 + 4]);
                } else {
                    a[mt][0] = tf32r(As[buf][rb][kk + c4]);
                    a[mt][1] = tf32r(As[buf][rb + 8][kk + c4]);
                    a[mt][2] = tf32r(As[buf][rb][kk + c4 + 4]);
                    a[mt][3] = tf32r(As[buf][rb + 8][kk + c4 + 4]);
                }
            }
#pragma unroll
            for (int nt = 0; nt < 4; nt++) {
                int nb = wn * 32 + nt * 8 + lr;
                // weights pre-rounded RNA -> in-MMA truncation is identity
                unsigned b0 = __float_as_uint(Ws[buf][nb][kk + c4]);
                unsigned b1 = __float_as_uint(Ws[buf][nb][kk + c4 + 4]);
#pragma unroll
                for (int mt = 0; mt < 2; mt++)
                    mma_tf32(c[mt][nt][0], c[mt][nt][1], c[mt][nt][2], c[mt][nt][3],
                             a[mt][0], a[mt][1], a[mt][2], a[mt][3], b0, b1);
            }
        }
    }

#pragma unroll
    for (int mt = 0; mt < 2; mt++) {
#pragma unroll
        for (int nt = 0; nt < 4; nt++) {
            int row = m0 + wm * 32 + mt * 16 + lr;
            int col = n0 + wn * 32 + nt * 8 + c4 * 2;
#pragma unroll
            for (int e = 0; e < 4; e++) {
                int rr = row + (e >> 1) * 8;
                int cc = col + (e & 1);
                float bv = nsplit ? ((cc < Kx) ? bias[cc] : bias2[cc - Kx]) : bias[cc];
                float v = c[mt][nt][e] + bv;
                if (flags & 1) v = fmaxf(v, 0.0f);
                if (flags & 4) v = sigm(v * E[(size_t)rr * eld + eoff + cc]);
                if (flags & 32) v = __uint_as_float(tf32r(v));
                C[(size_t)rr * N + cc] = v;
            }
        }
    }
}

// ---------------- fp16 bilinear v6: v5 + cva scalar register prefetch ----------
static constexpr int BIL5_SMEM_BYTES = (128 * 264 + 2 * 128 * 72) * 2;

__global__ void __launch_bounds__(256) bilinear5_kernel(
    const float* __restrict__ cva, const float* __restrict__ cav,
    const __half* __restrict__ Wh, float* __restrict__ part)
{
    extern __shared__ __half sh[];
    __half* s_cav = sh;                // [128][264]
    __half* s_W   = sh + 128 * 264;    // [2][128][72]

    const int tid = threadIdx.x;
    const int lane = tid & 31, wid = tid >> 5;
    const int wm = wid & 1, wn = wid >> 1;   // 2m(64) x 4n(32)
    const int g = lane >> 2, q = lane & 3;
    const int r0 = blockIdx.x * 128, o0 = blockIdx.y * 128;
    const int iBase = blockIdx.z * 64;

    for (int f = tid; f < 8192; f += 256) {
        int row = f >> 6, q4 = f & 63;
        float4 w = *(const float4*)(cav + (size_t)(r0 + row) * 256 + q4 * 4);
        __half* d = s_cav + row * 264 + q4 * 4;
        *(__half2*)(d)     = __floats2half2_rn(w.x, w.y);
        *(__half2*)(d + 2) = __floats2half2_rn(w.z, w.w);
    }

    float c[4][4][4];
#pragma unroll
    for (int mt = 0; mt < 4; mt++)
#pragma unroll
        for (int nt = 0; nt < 4; nt++)
#pragma unroll
            for (int e = 0; e < 4; e++) c[mt][nt][e] = 0.0f;

    auto issue_tile = [&](int it) {
        int i = iBase + (it >> 2), h = it & 3;
        __half* dst0 = s_W + (it & 1) * 128 * 72;
#pragma unroll
        for (int u = 0; u < 4; u++) {
            int cidx = tid + 256 * u;          // 0..1023
            int o = cidx >> 3, ch = cidx & 7;
            const __half* src = Wh + (size_t)(o0 + o) * 65536 + (size_t)i * 256 + h * 64 + ch * 8;
            cpa16(dst0 + o * 72 + ch * 8, src);
        }
        asm volatile("cp.async.commit_group;");
    };

    issue_tile(0);

    const int rb = wm * 64 + g;
    const float* cvaB = cva + (size_t)r0 * 256;

    // prefetch cva scalars for ig = iBase; rebuilt only when ig advances
    float spf[8];
#pragma unroll
    for (int mt = 0; mt < 4; mt++) {
        spf[2 * mt]     = cvaB[(size_t)(rb + mt * 16) * 256 + iBase];
        spf[2 * mt + 1] = cvaB[(size_t)(rb + mt * 16 + 8) * 256 + iBase];
    }
    __half2 s[8];
#pragma unroll
    for (int u = 0; u < 8; u++) s[u] = __half2half2(__float2half_rn(spf[u]));

    for (int it = 0; it < 256; it++) {
        asm volatile("cp.async.wait_group 0;");
        __syncthreads();
        if (it + 1 < 256) issue_tile(it + 1);

        const __half* wbuf = s_W + (it & 1) * 128 * 72;
        const int h = it & 3;
        const bool advance = (h == 3) && (it + 1 < 256);
        if (advance) {
            int ig2 = iBase + ((it + 1) >> 2);
#pragma unroll
            for (int mt = 0; mt < 4; mt++) {
                spf[2 * mt]     = cvaB[(size_t)(rb + mt * 16) * 256 + ig2];
                spf[2 * mt + 1] = cvaB[(size_t)(rb + mt * 16 + 8) * 256 + ig2];
            }
        }

#pragma unroll
        for (int jc = 0; jc < 4; jc++) {
            const int jlo = h * 64 + jc * 16 + 2 * q;
            const int jhi = jlo + 8;
            __half2 a[4][4];
#pragma unroll
            for (int mt = 0; mt < 4; mt++) {
                int r1 = rb + mt * 16, r2 = r1 + 8;
                a[mt][0] = __hmul2(*(__half2*)&s_cav[r1 * 264 + jlo], s[2 * mt]);
                a[mt][1] = __hmul2(*(__half2*)&s_cav[r2 * 264 + jlo], s[2 * mt + 1]);
                a[mt][2] = __hmul2(*(__half2*)&s_cav[r1 * 264 + jhi], s[2 * mt]);
                a[mt][3] = __hmul2(*(__half2*)&s_cav[r2 * 264 + jhi], s[2 * mt + 1]);
            }
            const int kloc = jc * 16;
#pragma unroll
            for (int nt = 0; nt < 4; nt++) {
                int oc = wn * 32 + nt * 8 + g;
                unsigned b0 = *(const unsigned*)&wbuf[oc * 72 + kloc + 2 * q];
                unsigned b1 = *(const unsigned*)&wbuf[oc * 72 + kloc + 2 * q + 8];
#pragma unroll
                for (int mt = 0; mt < 4; mt++)
                    mma_f16(c[mt][nt][0], c[mt][nt][1], c[mt][nt][2], c[mt][nt][3],
                            *(unsigned*)&a[mt][0], *(unsigned*)&a[mt][1],
                            *(unsigned*)&a[mt][2], *(unsigned*)&a[mt][3], b0, b1);
            }
        }
        if (advance) {
#pragma unroll
            for (int u = 0; u < 8; u++) s[u] = __half2half2(__float2half_rn(spf[u]));
        }
    }

    float* P = part + (size_t)blockIdx.z * N_BSD;
#pragma unroll
    for (int mt = 0; mt < 4; mt++) {
#pragma unroll
        for (int nt = 0; nt < 4; nt++) {
            int row = r0 + wm * 64 + mt * 16 + g;
            int col = o0 + wn * 32 + nt * 8 + q * 2;
            float* d0 = P + (size_t)row * 256 + col;
            float* d1 = P + (size_t)(row + 8) * 256 + col;
            d0[0] = c[mt][nt][0]; d0[1] = c[mt][nt][1];
            d1[0] = c[mt][nt][2]; d1[1] = c[mt][nt][3];
        }
    }
}

// finish
__global__ void bil_finish_kernel(const float* __restrict__ part,
                                  const float* __restrict__ xv, const float* __restrict__ xa,
                                  const float* __restrict__ tcp,
                                  const float* __restrict__ mv, const float* __restrict__ ma,
                                  float* __restrict__ o1, float* __restrict__ o2)
{
    int i = blockIdx.x * 256 + threadIdx.x;
    float s = part[i] + part[i + N_BSD] + part[i + 2 * N_BSD] + part[i + 3 * N_BSD];
    float j = sigm(s);
    float m = (*tcp) * j * xv[i] + (1.0f - j) * xa[i];
    o1[i] = m * mv[i];
    o2[i] = m * ma[i];
}

// ---------------- attention (writes cat pre-rounded to RNA-tf32) ----------------
__global__ void __launch_bounds__(256) attn_kernel(
    const float* __restrict__ xv, const float* __restrict__ xa,
    const float* __restrict__ qkv_v, const float* __restrict__ qkv_a,
    float* __restrict__ cat1, float* __restrict__ cat2)
{
    __shared__ float s_x[2][3][256];
    __shared__ float s_q[2][3][256];
    __shared__ float s_k[2][3][256];
    __shared__ float s_sc[4][3][3];
    const int tid = threadIdx.x;
    const size_t base = (size_t)blockIdx.x * 768;
    const size_t base2 = (size_t)blockIdx.x * 1536;
    const size_t qbase = (size_t)blockIdx.x * 3 * 512;

    float* fx = &s_x[0][0][0];
    float* fq = &s_q[0][0][0];
    float* fk = &s_k[0][0][0];
    for (int idx = tid; idx < 768; idx += 256) {
        int s3 = idx >> 8, d = idx & 255;
        size_t qoff = qbase + (size_t)s3 * 512 + d;
        fx[idx] = xv[base + idx]; fx[768 + idx] = xa[base + idx];
        fq[idx] = qkv_v[qoff];        fq[768 + idx] = qkv_a[qoff];
        fk[idx] = qkv_v[qoff + 256];  fk[768 + idx] = qkv_a[qoff + 256];
    }
    __syncthreads();

    const int w = tid >> 5, lane = tid & 31;
    for (int task = w; task < 36; task += 8) {
        int type = task / 9, rem = task % 9, s3 = rem / 3, t3 = rem % 3;
        int qsel = type >> 1;
        int ksel = (type == 0 || type == 3) ? 1 : 0;
        float sum = 0.0f;
        for (int d = lane; d < 256; d += 32) sum += s_q[qsel][s3][d] * s_k[ksel][t3][d];
#pragma unroll
        for (int off = 16; off; off >>= 1) sum += __shfl_down_sync(0xffffffffu, sum, off);
        if (lane == 0) s_sc[type][s3][t3] = sum;
    }
    __syncthreads();

    if (tid < 12) {
        int type = tid / 3, s3 = tid % 3;
        float a = s_sc[type][s3][0], b = s_sc[type][s3][1], c = s_sc[type][s3][2];
        float m = fmaxf(a, fmaxf(b, c));
        float ea = expf(a - m), eb = expf(b - m), ec = expf(c - m);
        float inv = 0.0625f / (ea + eb + ec);
        s_sc[type][s3][0] = ea * inv; s_sc[type][s3][1] = eb * inv; s_sc[type][s3][2] = ec * inv;
    }
    __syncthreads();

    for (int idx = tid; idx < 3072; idx += 256) {
        int type = idx / 768, rem = idx % 768;
        int s3 = rem >> 8, d = rem & 255;
        int xsel = (type == 0 || type == 3) ? 1 : 0;
        float v = s_sc[type][s3][0] * s_x[xsel][0][d]
                + s_sc[type][s3][1] * s_x[xsel][1][d]
                + s_sc[type][s3][2] * s_x[xsel][2][d];
        float* dst = (type < 2) ? cat1 : cat2;
        dst[base2 + (size_t)s3 * 512 + ((type & 1) ? 256 : 0) + d] =
            __uint_as_float(tf32r(v));
    }
}

// ---------------- classifier (z-batched) ----------------
struct CLSB { const float* W1[2]; const float* W2[2]; };

__global__ void __launch_bounds__(256) cls_kernel(
    const float* __restrict__ Fbase, CLSB P, float* __restrict__ Pbase)
{
    __shared__ float s_f[8][128];
    __shared__ float s_w1[32][129];
    __shared__ float s_w2[320];
    __shared__ float s_h[8][32];
    const int z = blockIdx.y;
    const float* F = Fbase + (size_t)z * Bn * LAT;
    const float* W1 = P.W1[z];
    const float* W2 = P.W2[z];
    float* Pout = Pbase + (size_t)z * Bn * 10;

    const int tid = threadIdx.x;
    const int r0 = blockIdx.x * 8;
    for (int idx = tid; idx < 1024; idx += 256) s_f[idx >> 7][idx & 127] = F[(size_t)r0 * 128 + idx];
    for (int idx = tid; idx < 4096; idx += 256) s_w1[idx >> 7][idx & 127] = W1[idx];
    for (int idx = tid; idx < 320; idx += 256) s_w2[idx] = W2[idx];
    __syncthreads();
    const int w = tid >> 5, lane = tid & 31;
    float h = 0.0f;
#pragma unroll 8
    for (int d = 0; d < 128; d++) h = fmaf(s_f[w][d], s_w1[lane][d], h);
    s_h[w][lane] = fmaxf(h, 0.0f);
    __syncwarp();
    if (lane < 10) {
        float p = 0.0f;
#pragma unroll
        for (int k = 0; k < 32; k++) p = fmaf(s_h[w][k], s_w2[lane * 32 + k], p);
        Pout[(size_t)(r0 + w) * 10 + lane] = p;
    }
}

// ---------------- host ----------------
extern "C" void kernel_launch(void* const* d_in, const int* in_sizes, int n_in,
                              void* d_out, int out_size)
{
    const float* img    = (const float*)d_in[0];
    const float* audio  = (const float*)d_in[1];
    const float* vis_W  = (const float*)d_in[2];
    const float* vis_b  = (const float*)d_in[3];
    const float* aud_W  = (const float*)d_in[4];
    const float* aud_b  = (const float*)d_in[5];
    const float* msv_W  = (const float*)d_in[6];
    const float* msv_b  = (const float*)d_in[7];
    const float* msa_W  = (const float*)d_in[8];
    const float* msa_b  = (const float*)d_in[9];
    const float* mmfaW  = (const float*)d_in[10];
    const float* mmfaB  = (const float*)d_in[11];
    const float* bilW   = (const float*)d_in[12];
    const float* t_c    = (const float*)d_in[13];
    const float* out_W1 = (const float*)d_in[14];
    const float* out_b1 = (const float*)d_in[15];
    const float* out_W2 = (const float*)d_in[16];
    const float* out_b2 = (const float*)d_in[17];
    const float* clsvW1 = (const float*)d_in[18];
    const float* clsvW2 = (const float*)d_in[19];
    const float* clsaW1 = (const float*)d_in[20];
    const float* clsaW2 = (const float*)d_in[21];

    float* S = nullptr;
    cudaGetSymbolAddress((void**)&S, g_scratch);
    float* p_bf = nullptr;
    cudaGetSymbolAddress((void**)&p_bf, g_bias_fused);
    __half* p_Wh = nullptr;
    cudaGetSymbolAddress((void**)&p_Wh, g_Wh);

    float* p_vis  = S;
    float* p_aud  = p_vis + N_BE;
    float* p_vms  = p_aud + N_BE;
    float* p_ams  = p_vms + N_BSD;
    float* p_qkv  = p_ams + N_BSD;        // [3072][512]
    float* p_qka  = p_qkv + 2 * N_BSD;    // [3072][512]
    float* p_cat1 = p_qka + 2 * N_BSD;    // [3072][512]
    float* p_cat2 = p_cat1 + 2 * N_BSD;   // [3072][512]
    float* p_cva  = p_cat2 + 2 * N_BSD;
    float* p_cav  = p_cva + N_BSD;
    float* p_bp   = p_cav + N_BSD;        // 4 x [3072][256]
    float* p_xv   = p_bp  + 4 * N_BSD;
    float* p_xa   = p_xv  + N_BSD;
    float* p_ov   = p_xa  + N_BSD;        // ov/oa contiguous -> [2048][768]
    float* p_oa   = p_ov  + N_BSD;
    float* p_h    = p_oa  + N_BSD;        // [2048][512]
    // RNA-pre-rounded weight copies
    float* wr_mmfa = p_h + (size_t)2 * Bn * OUT1;   // 2097152
    float* wr_msv  = wr_mmfa + 2097152;             // 786432
    float* wr_msa  = wr_msv + 786432;               // 786432
    float* wr_o1   = wr_msa + 786432;               // 393216
    float* wr_o2   = wr_o1 + 393216;                // 65536

    const int nBlk = (int)(N_BSD / 256);

    cudaFuncSetAttribute(bilinear5_kernel,
                         cudaFuncAttributeMaxDynamicSharedMemorySize, BIL5_SMEM_BYTES);

    fuse_bias_kernel<<<1, 256>>>(mmfaB, p_bf);
    wconv_kernel<<<16384, 256>>>(bilW, p_Wh);
    wround_kernel<<<2048, 256>>>(mmfaW, wr_mmfa);
    wround_kernel<<<768, 256>>>(msv_W, wr_msv);
    wround_kernel<<<768, 256>>>(msa_W, wr_msa);
    wround_kernel<<<384, 256>>>(out_W1, wr_o1);
    wround_kernel<<<64, 256>>>(out_W2, wr_o2);
    float* p_b45 = p_bf;
    float* p_b67 = p_bf + 256;

    auto run_mmfa = [&](const float* xv, const float* xa,
                        const float* mv, const float* ma, float* o1, float* o2) {
        GB qk;
        qk.A[0] = xv;  qk.W[0] = wr_mmfa + 0 * 65536; qk.W2[0] = wr_mmfa + 2 * 65536;
        qk.b1[0] = mmfaB + 0 * 256; qk.b2[0] = mmfaB + 2 * 256; qk.E[0] = xv;  qk.C[0] = p_qkv;
        qk.A[1] = xa;  qk.W[1] = wr_mmfa + 1 * 65536; qk.W2[1] = wr_mmfa + 3 * 65536;
        qk.b1[1] = mmfaB + 1 * 256; qk.b2[1] = mmfaB + 3 * 256; qk.E[1] = xa;  qk.C[1] = p_qka;
        mma_gemm_kernel<<<dim3(512 / 64, M3 / 128, 2), 256>>>(qk, M3, 512, Dd, 256, 8, 0, 0);

        attn_kernel<<<Bn, 256>>>(xv, xa, p_qkv, p_qka, p_cat1, p_cat2);

        GB cc;
        cc.A[0] = p_cat1; cc.W[0] = wr_mmfa + 4 * 65536; cc.W2[0] = wr_mmfa + 5 * 65536;
        cc.b1[0] = p_b45; cc.b2[0] = p_b45; cc.E[0] = p_cat1; cc.C[0] = p_cva;
        cc.A[1] = p_cat2; cc.W[1] = wr_mmfa + 6 * 65536; cc.W2[1] = wr_mmfa + 7 * 65536;
        cc.b1[1] = p_b67; cc.b2[1] = p_b67; cc.E[1] = p_cat2; cc.C[1] = p_cav;
        mma_gemm_kernel<<<dim3(256 / 64, M3 / 128, 2), 256>>>(cc, M3, Dd, 512, 256, 4 | 16, 512, 256);

        bilinear5_kernel<<<dim3(24, 2, 4), 256, BIL5_SMEM_BYTES>>>(p_cva, p_cav, p_Wh, p_bp);
        bil_finish_kernel<<<nBlk, 256>>>(p_bp, xv, xa, t_c, mv, ma, o1, o2);
    };

    // encoders (vis||aud) fp32 SIMT with register prefetch
    {
        GB32 e;
        e.A[0] = img;   e.W[0] = vis_W; e.b[0] = vis_b; e.C[0] = p_vis; e.K[0] = 4096;
        e.A[1] = audio; e.W[1] = aud_W; e.b[1] = aud_b; e.C[1] = p_aud; e.K[1] = 1024;
        gemm_kernel<<<dim3(16, 8, 2), 256>>>(e, Bn, 1024, 1);
    }

    // multi-scale -> tf32 RNA tensor path (weights pre-rounded)
    {
        GB m;
        m.A[0] = p_vis; m.W[0] = m.W2[0] = wr_msv; m.b1[0] = m.b2[0] = msv_b;
        m.E[0] = p_vis; m.C[0] = p_vms;
        m.A[1] = p_aud; m.W[1] = m.W2[1] = wr_msa; m.b1[1] = m.b2[1] = msa_b;
        m.E[1] = p_aud; m.C[1] = p_ams;
        mma_gemm_kernel<<<dim3(SD / 64, Bn / 128, 2), 256>>>(m, Bn, SD, 1024, 1024, 1, 0, 0);
    }

    run_mmfa(p_vms, p_ams, p_vms, p_ams, p_xv, p_xa);
    run_mmfa(p_xv, p_xa, p_vms, p_ams, p_ov, p_oa);

    float* out = (float*)d_out;
    float* fv = out;
    float* fa = out + (size_t)Bn * LAT;
    float* pv = fa + (size_t)Bn * LAT;

    // out_layer M-batched over (ov||oa) -> (fv||fa)
    {
        GB o1;
        o1.A[0] = o1.A[1] = p_ov; o1.W[0] = o1.W[1] = wr_o1; o1.W2[0] = o1.W2[1] = wr_o1;
        o1.b1[0] = o1.b1[1] = out_b1; o1.b2[0] = o1.b2[1] = out_b1;
        o1.E[0] = o1.E[1] = p_ov; o1.C[0] = o1.C[1] = p_h;
        // relu + round output to tf32 (consumed only by o2, which would round anyway)
        mma_gemm_kernel<<<dim3(OUT1 / 64, 2 * Bn / 128, 1), 256>>>(o1, 2 * Bn, OUT1, SD, SD, 1 | 32, 0, 0);

        GB o2;
        o2.A[0] = o2.A[1] = p_h; o2.W[0] = o2.W[1] = wr_o2; o2.W2[0] = o2.W2[1] = wr_o2;
        o2.b1[0] = o2.b1[1] = out_b2; o2.b2[0] = o2.b2[1] = out_b2;
        o2.E[0] = o2.E[1] = p_h; o2.C[0] = o2.C[1] = fv;
        mma_gemm_kernel<<<dim3(LAT / 64, 2 * Bn / 128, 1), 256>>>(o2, 2 * Bn, LAT, OUT1, OUT1, 16, 0, 0);
    }

    // classifiers batched (z=2)
    {
        CLSB cb;
        cb.W1[0] = clsvW1; cb.W2[0] = clsvW2;
        cb.W1[1] = clsaW1; cb.W2[1] = clsaW2;
        cls_kernel<<<dim3(Bn / 8, 2), 256>>>(fv, cb, pv);
    }
}

// round 15
// speedup vs baseline: 1.3100x; 1.1652x over previous
#include <cuda_runtime.h>
#include <cuda_fp16.h>
#include <math.h>
#include <stdint.h>

// ---------------- problem constants ----------------
static constexpr int Bn   = 1024;
static constexpr int M3   = 3072;   // B*S
static constexpr int Dd   = 256;
static constexpr int SD   = 768;
static constexpr int OUT1 = 512;
static constexpr int LAT  = 128;

static constexpr size_t N_BE  = (size_t)Bn * 1024;
static constexpr size_t N_BSD = (size_t)M3 * Dd;     // 786432

__device__ float g_scratch[2 * N_BE + 26 * N_BSD + (size_t)Bn * OUT1];
__device__ float g_bias_fused[512];            // [0:256)=b4+b5, [256:512)=b6+b7
__device__ __half g_Wh[16777216];              // bil_W in fp16 (32MB)

__device__ __forceinline__ float sigm(float x) { return 1.0f / (1.0f + expf(-x)); }

__device__ __forceinline__ unsigned tf32r(float x) {
    unsigned r;
    asm("cvt.rna.tf32.f32 %0, %1;" : "=r"(r) : "f"(x));
    return r;
}

__device__ __forceinline__ void mma_tf32(float& c0, float& c1, float& c2, float& c3,
                                         unsigned a0, unsigned a1, unsigned a2, unsigned a3,
                                         unsigned b0, unsigned b1) {
    asm("mma.sync.aligned.m16n8k8.row.col.f32.tf32.tf32.f32 "
        "{%0,%1,%2,%3}, {%4,%5,%6,%7}, {%8,%9}, {%0,%1,%2,%3};"
        : "+f"(c0), "+f"(c1), "+f"(c2), "+f"(c3)
        : "r"(a0), "r"(a1), "r"(a2), "r"(a3), "r"(b0), "r"(b1));
}

__device__ __forceinline__ void mma_f16(float& c0, float& c1, float& c2, float& c3,
                                        unsigned a0, unsigned a1, unsigned a2, unsigned a3,
                                        unsigned b0, unsigned b1) {
    asm("mma.sync.aligned.m16n8k16.row.col.f32.f16.f16.f32 "
        "{%0,%1,%2,%3}, {%4,%5,%6,%7}, {%8,%9}, {%0,%1,%2,%3};"
        : "+f"(c0), "+f"(c1), "+f"(c2), "+f"(c3)
        : "r"(a0), "r"(a1), "r"(a2), "r"(a3), "r"(b0), "r"(b1));
}

__device__ __forceinline__ void cpa16(void* smem_dst, const void* gsrc) {
    unsigned sa = (unsigned)__cvta_generic_to_shared(smem_dst);
    asm volatile("cp.async.cg.shared.global [%0], [%1], 16;" :: "r"(sa), "l"(gsrc));
}

// ---------------- helpers ----------------
__global__ void fuse_bias_kernel(const float* __restrict__ b, float* __restrict__ o)
{
    int i = threadIdx.x;
    o[i]       = b[4 * 256 + i] + b[5 * 256 + i];
    o[256 + i] = b[6 * 256 + i] + b[7 * 256 + i];
}

__global__ void wconv_kernel(const float* __restrict__ W, __half* __restrict__ Wh)
{
    size_t i = ((size_t)blockIdx.x * 256 + threadIdx.x) * 4;
    float4 v = *(const float4*)(W + i);
    *(__half2*)(Wh + i)     = __floats2half2_rn(v.x, v.y);
    *(__half2*)(Wh + i + 2) = __floats2half2_rn(v.z, v.w);
}

// copy with RNA-tf32 rounding (weights for tf32 GEMMs): in-MMA RZ becomes identity
__global__ void wround_kernel(const float* __restrict__ src, float* __restrict__ dst)
{
    size_t i = ((size_t)blockIdx.x * 256 + threadIdx.x) * 4;
    float4 v = *(const float4*)(src + i);
    float4 o;
    o.x = __uint_as_float(tf32r(v.x));
    o.y = __uint_as_float(tf32r(v.y));
    o.z = __uint_as_float(tf32r(v.z));
    o.w = __uint_as_float(tf32r(v.w));
    *(float4*)(dst + i) = o;
}

// ---------------- fp32 SIMT GEMM, z-batched (encoders), register-prefetch --------
struct GB32 {
    const float* A[2]; const float* W[2]; const float* b[2]; float* C[2]; int K[2];
};

__global__ void __launch_bounds__(256) gemm_kernel(GB32 P, int M, int N, int flags)
{
    __shared__ __align__(16) float As[16][132];
    __shared__ __align__(16) float Ws[16][68];
    const int z = blockIdx.z;
    const float* A = P.A[z];
    const float* W = P.W[z];
    const float* bias = P.b[z];
    float* C = P.C[z];
    const int K = P.K[z];

    const int tid = threadIdx.x;
    const int tx = tid & 15, ty = tid >> 4;
    const int m0 = blockIdx.y * 128, n0 = blockIdx.x * 64;
    const int lrow = tid >> 2, lk = (tid & 3) << 2;

    const float* Ag0 = A + (size_t)(m0 + lrow) * K + lk;
    const float* Ag1 = A + (size_t)(m0 + lrow + 64) * K + lk;
    const float* Wg  = W + (size_t)(n0 + lrow) * K + lk;

    float4 a0 = *(const float4*)(Ag0);
    float4 a1 = *(const float4*)(Ag1);
    float4 w0 = *(const float4*)(Wg);

    float acc[8][4] = {};
    for (int kt = 0; kt < K; kt += 16) {
        As[lk + 0][lrow] = a0.x; As[lk + 1][lrow] = a0.y;
        As[lk + 2][lrow] = a0.z; As[lk + 3][lrow] = a0.w;
        As[lk + 0][lrow + 64] = a1.x; As[lk + 1][lrow + 64] = a1.y;
        As[lk + 2][lrow + 64] = a1.z; As[lk + 3][lrow + 64] = a1.w;
        Ws[lk + 0][lrow] = w0.x; Ws[lk + 1][lrow] = w0.y;
        Ws[lk + 2][lrow] = w0.z; Ws[lk + 3][lrow] = w0.w;
        __syncthreads();
        if (kt + 16 < K) {
            a0 = *(const float4*)(Ag0 + kt + 16);
            a1 = *(const float4*)(Ag1 + kt + 16);
            w0 = *(const float4*)(Wg + kt + 16);
        }
#pragma unroll
        for (int k = 0; k < 16; k++) {
            float ar[8];
            *(float4*)&ar[0] = *(const float4*)&As[k][ty * 8];
            *(float4*)&ar[4] = *(const float4*)&As[k][ty * 8 + 4];
            float4 b = *(const float4*)&Ws[k][tx * 4];
#pragma unroll
            for (int i = 0; i < 8; i++) {
                acc[i][0] = fmaf(ar[i], b.x, acc[i][0]);
                acc[i][1] = fmaf(ar[i], b.y, acc[i][1]);
                acc[i][2] = fmaf(ar[i], b.z, acc[i][2]);
                acc[i][3] = fmaf(ar[i], b.w, acc[i][3]);
            }
        }
        __syncthreads();
    }
#pragma unroll
    for (int i = 0; i < 8; i++) {
        int row = m0 + ty * 8 + i;
#pragma unroll
        for (int j = 0; j < 4; j++) {
            int col = n0 + tx * 4 + j;
            float v = acc[i][j] + bias[col];
            if (flags & 1) v = fmaxf(v, 0.0f);
            C[(size_t)row * N + col] = v;
        }
    }
}

// ---------------- tf32 tensor GEMM v4: 3-stage cp.async; weights pre-rounded -------
// flags: bit0 relu ; bit2 sigmul ; bit3 N-split ; bit4 A pre-rounded ; bit5 round output
struct GB {
    const float* A[2]; const float* W[2]; const float* W2[2];
    const float* b1[2]; const float* b2[2]; const float* E[2]; float* C[2];
};

__global__ void __launch_bounds__(256) mma_gemm_kernel(
    GB P, int M, int N, int K, int Kx, int flags, int eld, int eoff)
{
    __shared__ __align__(16) float As[3][128][20];
    __shared__ __align__(16) float Ws[3][64][20];
    const int z = blockIdx.z;
    const float* A = P.A[z];
    const float* W = P.W[z];
    const float* W2 = P.W2[z];
    const float* bias = P.b1[z];
    const float* bias2 = P.b2[z];
    const float* E = P.E[z];
    float* C = P.C[z];

    const int tid = threadIdx.x;
    const int lane = tid & 31, wid = tid >> 5;
    const int wm = wid >> 1, wn = wid & 1;
    const int m0 = blockIdx.y * 128, n0 = blockIdx.x * 64;
    const int c4 = lane & 3, lr = lane >> 2;
    const int Kb = K - Kx;
    const bool nsplit = (flags & 8) != 0;
    const bool a_ready = (flags & 16) != 0;

    float c[2][4][4];
#pragma unroll
    for (int mt = 0; mt < 2; mt++)
#pragma unroll
        for (int nt = 0; nt < 4; nt++)
#pragma unroll
            for (int e = 0; e < 4; e++) c[mt][nt][e] = 0.0f;

    const int arow0 = tid >> 2, ach = tid & 3;
    auto issue_tile = [&](int kt) {
        int buf = kt % 3;
        int kbase = kt * 16;
#pragma unroll
        for (int u = 0; u < 2; u++) {
            int chunk = tid + 256 * u;
            int row = chunk >> 2, ch = chunk & 3;
            cpa16(&As[buf][row][ch * 4], A + (size_t)(m0 + row) * K + kbase + ch * 4);
        }
        {
            int row = arow0, ch = ach;
            int k = kbase + ch * 4;
            const float* ws;
            if (nsplit) {
                int n = n0 + row;
                ws = (n < Kx) ? (W + (size_t)n * K + k) : (W2 + (size_t)(n - Kx) * K + k);
            } else {
                ws = (k < Kx) ? (W + (size_t)(n0 + row) * Kx + k)
                              : (W2 + (size_t)(n0 + row) * Kb + (k - Kx));
            }
            cpa16(&Ws[buf][row][ch * 4], ws);
        }
        asm volatile("cp.async.commit_group;");
    };

    const int ktiles = K >> 4;
    issue_tile(0);
    if (ktiles > 1) issue_tile(1);

    const int rbB = wm * 32 + lr;
    for (int kt = 0; kt < ktiles; kt++) {
        if (kt + 1 < ktiles) asm volatile("cp.async.wait_group 1;" ::: "memory");
        else                 asm volatile("cp.async.wait_group 0;" ::: "memory");
        __syncthreads();
        if (kt + 2 < ktiles) issue_tile(kt + 2);
        const int buf = kt % 3;
#pragma unroll
        for (int kk = 0; kk < 16; kk += 8) {
            unsigned a[2][4];
#pragma unroll
            for (int mt = 0; mt < 2; mt++) {
                int rb = rbB + mt * 16;
                if (a_ready) {
                    a[mt][0] = __float_as_uint(As[buf][rb][kk + c4]);
                    a[mt][1] = __float_as_uint(As[buf][rb + 8][kk + c4]);
                    a[mt][2] = __float_as_uint(As[buf][rb][kk + c4 + 4]);
                    a[mt][3] = __float_as_uint(As[buf][rb + 8][kk + c4 + 4]);
                } else {
                    a[mt][0] = tf32r(As[buf][rb][kk + c4]);
                    a[mt][1] = tf32r(As[buf][rb + 8][kk + c4]);
                    a[mt][2] = tf32r(As[buf][rb][kk + c4 + 4]);
                    a[mt][3] = tf32r(As[buf][rb + 8][kk + c4 + 4]);
                }
            }
#pragma unroll
            for (int nt = 0; nt < 4; nt++) {
                int nb = wn * 32 + nt * 8 + lr;
                unsigned b0 = __float_as_uint(Ws[buf][nb][kk + c4]);
                unsigned b1 = __float_as_uint(Ws[buf][nb][kk + c4 + 4]);
#pragma unroll
                for (int mt = 0; mt < 2; mt++)
                    mma_tf32(c[mt][nt][0], c[mt][nt][1], c[mt][nt][2], c[mt][nt][3],
                             a[mt][0], a[mt][1], a[mt][2], a[mt][3], b0, b1);
            }
        }
    }

#pragma unroll
    for (int mt = 0; mt < 2; mt++) {
#pragma unroll
        for (int nt = 0; nt < 4; nt++) {
            int row = m0 + wm * 32 + mt * 16 + lr;
            int col = n0 + wn * 32 + nt * 8 + c4 * 2;
#pragma unroll
            for (int e = 0; e < 4; e++) {
                int rr = row + (e >> 1) * 8;
                int cc = col + (e & 1);
                float bv = nsplit ? ((cc < Kx) ? bias[cc] : bias2[cc - Kx]) : bias[cc];
                float v = c[mt][nt][e] + bv;
                if (flags & 1) v = fmaxf(v, 0.0f);
                if (flags & 4) v = sigm(v * E[(size_t)rr * eld + eoff + cc]);
                if (flags & 32) v = __uint_as_float(tf32r(v));
                C[(size_t)rr * N + cc] = v;
            }
        }
    }
}

// ---------------- fp16 bilinear v7b: o-tile 64, K-split 3 (85/85/86), 3-deep W ring ----
// grid (24, 4, 3): r-block 128, o-block 64, z -> i-ranges {0:85, 85:85, 170:86}.
// 256 threads = 8 warps (4m x 2n), warp tile 32x32.
// smem: s_cav [128][264] fp16 (67584B) + s_W [3][64][72] fp16 (27648B) = 95232B -> 2/SM
static constexpr int BIL7_SMEM_BYTES = (128 * 264 + 3 * 64 * 72) * 2;

__global__ void __launch_bounds__(256) bilinear7_kernel(
    const float* __restrict__ cva, const float* __restrict__ cav,
    const __half* __restrict__ Wh, float* __restrict__ part)
{
    extern __shared__ __half sh[];
    __half* s_cav = sh;                // [128][264]
    __half* s_W   = sh + 128 * 264;    // [3][64][72]

    const int tid = threadIdx.x;
    const int lane = tid & 31, wid = tid >> 5;
    const int wm = wid >> 1, wn = wid & 1;   // 4m(32) x 2n(32)
    const int g = lane >> 2, q = lane & 3;
    const int r0 = blockIdx.x * 128, o0 = blockIdx.y * 64;
    const int z = blockIdx.z;
    const int iStart = (z < 2) ? z * 85 : 170;   // 85 + 85 + 86 = 256
    const int iCnt   = (z < 2) ? 85 : 86;
    const int T = iCnt * 4;

    for (int f = tid; f < 8192; f += 256) {
        int row = f >> 6, q4 = f & 63;
        float4 w = *(const float4*)(cav + (size_t)(r0 + row) * 256 + q4 * 4);
        __half* d = s_cav + row * 264 + q4 * 4;
        *(__half2*)(d)     = __floats2half2_rn(w.x, w.y);
        *(__half2*)(d + 2) = __floats2half2_rn(w.z, w.w);
    }

    float c[2][4][4];
#pragma unroll
    for (int mt = 0; mt < 2; mt++)
#pragma unroll
        for (int nt = 0; nt < 4; nt++)
#pragma unroll
            for (int e = 0; e < 4; e++) c[mt][nt][e] = 0.0f;

    // W tile: 64 o x 64 j halves = 8KB = 512 x 16B chunks, 2 per thread
    auto issue_tile = [&](int t) {
        int i = iStart + (t >> 2), h = t & 3;
        __half* dst0 = s_W + (t % 3) * 64 * 72;
#pragma unroll
        for (int u = 0; u < 2; u++) {
            int cidx = tid + 256 * u;          // 0..511
            int o = cidx >> 3, ch = cidx & 7;
            const __half* src = Wh + (size_t)(o0 + o) * 65536 + (size_t)i * 256 + h * 64 + ch * 8;
            cpa16(dst0 + o * 72 + ch * 8, src);
        }
        asm volatile("cp.async.commit_group;");
    };

    issue_tile(0);
    issue_tile(1);

    const int rb = wm * 32 + g;
    const float* cvaB = cva + (size_t)r0 * 256;

    // prefetch cva scalars (4 rows per thread) for i = iStart
    float spf[4];
#pragma unroll
    for (int mt = 0; mt < 4; mt++)
        spf[mt] = cvaB[(size_t)(rb + mt * 8) * 256 + iStart];
    __half2 s[4];
#pragma unroll
    for (int u = 0; u < 4; u++) s[u] = __half2half2(__float2half_rn(spf[u]));

    for (int t = 0; t < T; t++) {
        if (t + 1 < T) asm volatile("cp.async.wait_group 1;" ::: "memory");
        else           asm volatile("cp.async.wait_group 0;" ::: "memory");
        __syncthreads();   // tile t + s_cav visible; compute(t-1) done everywhere
        if (t + 2 < T) issue_tile(t + 2);

        const __half* wbuf = s_W + (t % 3) * 64 * 72;
        const int h = t & 3;
        const bool advance = (h == 3) && (t + 1 < T);
        if (advance) {
            int ig2 = iStart + ((t + 1) >> 2);
#pragma unroll
            for (int mt = 0; mt < 4; mt++)
                spf[mt] = cvaB[(size_t)(rb + mt * 8) * 256 + ig2];
        }

#pragma unroll
        for (int jc = 0; jc < 4; jc++) {
            const int jlo = h * 64 + jc * 16 + 2 * q;
            const int jhi = jlo + 8;
            __half2 a[2][4];
#pragma unroll
            for (int mt = 0; mt < 2; mt++) {
                int r1 = rb + mt * 16, r2 = r1 + 8;
                a[mt][0] = __hmul2(*(__half2*)&s_cav[r1 * 264 + jlo], s[2 * mt]);
                a[mt][1] = __hmul2(*(__half2*)&s_cav[r2 * 264 + jlo], s[2 * mt + 1]);
                a[mt][2] = __hmul2(*(__half2*)&s_cav[r1 * 264 + jhi], s[2 * mt]);
                a[mt][3] = __hmul2(*(__half2*)&s_cav[r2 * 264 + jhi], s[2 * mt + 1]);
            }
            const int kloc = jc * 16;
#pragma unroll
            for (int nt = 0; nt < 4; nt++) {
                int oc = wn * 32 + nt * 8 + g;
                unsigned b0 = *(const unsigned*)&wbuf[oc * 72 + kloc + 2 * q];
                unsigned b1 = *(const unsigned*)&wbuf[oc * 72 + kloc + 2 * q + 8];
#pragma unroll
                for (int mt = 0; mt < 2; mt++)
                    mma_f16(c[mt][nt][0], c[mt][nt][1], c[mt][nt][2], c[mt][nt][3],
                            *(unsigned*)&a[mt][0], *(unsigned*)&a[mt][1],
                            *(unsigned*)&a[mt][2], *(unsigned*)&a[mt][3], b0, b1);
            }
        }
        if (advance) {
#pragma unroll
            for (int u = 0; u < 4; u++) s[u] = __half2half2(__float2half_rn(spf[u]));
        }
    }

    float* P = part + (size_t)z * N_BSD;
#pragma unroll
    for (int mt = 0; mt < 2; mt++) {
#pragma unroll
        for (int nt = 0; nt < 4; nt++) {
            int row = r0 + wm * 32 + mt * 16 + g;
            int col = o0 + wn * 32 + nt * 8 + q * 2;
            float* d0 = P + (size_t)row * 256 + col;
            float* d1 = P + (size_t)(row + 8) * 256 + col;
            d0[0] = c[mt][nt][0]; d0[1] = c[mt][nt][1];
            d1[0] = c[mt][nt][2]; d1[1] = c[mt][nt][3];
        }
    }
}

// finish: j = sigm(sum of 3 partials); m = tc*j*xv + (1-j)*xa; o1 = m*mv; o2 = m*ma
__global__ void bil_finish_kernel(const float* __restrict__ part,
                                  const float* __restrict__ xv, const float* __restrict__ xa,
                                  const float* __restrict__ tcp,
                                  const float* __restrict__ mv, const float* __restrict__ ma,
                                  float* __restrict__ o1, float* __restrict__ o2)
{
    int i = blockIdx.x * 256 + threadIdx.x;
    float s = part[i] + part[i + N_BSD] + part[i + 2 * N_BSD];
    float j = sigm(s);
    float m = (*tcp) * j * xv[i] + (1.0f - j) * xa[i];
    o1[i] = m * mv[i];
    o2[i] = m * ma[i];
}

// ---------------- attention (writes cat pre-rounded to RNA-tf32) ----------------
__global__ void __launch_bounds__(256) attn_kernel(
    const float* __restrict__ xv, const float* __restrict__ xa,
    const float* __restrict__ qkv_v, const float* __restrict__ qkv_a,
    float* __restrict__ cat1, float* __restrict__ cat2)
{
    __shared__ float s_x[2][3][256];
    __shared__ float s_q[2][3][256];
    __shared__ float s_k[2][3][256];
    __shared__ float s_sc[4][3][3];
    const int tid = threadIdx.x;
    const size_t base = (size_t)blockIdx.x * 768;
    const size_t base2 = (size_t)blockIdx.x * 1536;
    const size_t qbase = (size_t)blockIdx.x * 3 * 512;

    float* fx = &s_x[0][0][0];
    float* fq = &s_q[0][0][0];
    float* fk = &s_k[0][0][0];
    for (int idx = tid; idx < 768; idx += 256) {
        int s3 = idx >> 8, d = idx & 255;
        size_t qoff = qbase + (size_t)s3 * 512 + d;
        fx[idx] = xv[base + idx]; fx[768 + idx] = xa[base + idx];
        fq[idx] = qkv_v[qoff];        fq[768 + idx] = qkv_a[qoff];
        fk[idx] = qkv_v[qoff + 256];  fk[768 + idx] = qkv_a[qoff + 256];
    }
    __syncthreads();

    const int w = tid >> 5, lane = tid & 31;
    for (int task = w; task < 36; task += 8) {
        int type = task / 9, rem = task % 9, s3 = rem / 3, t3 = rem % 3;
        int qsel = type >> 1;
        int ksel = (type == 0 || type == 3) ? 1 : 0;
        float sum = 0.0f;
        for (int d = lane; d < 256; d += 32) sum += s_q[qsel][s3][d] * s_k[ksel][t3][d];
#pragma unroll
        for (int off = 16; off; off >>= 1) sum += __shfl_down_sync(0xffffffffu, sum, off);
        if (lane == 0) s_sc[type][s3][t3] = sum;
    }
    __syncthreads();

    if (tid < 12) {
        int type = tid / 3, s3 = tid % 3;
        float a = s_sc[type][s3][0], b = s_sc[type][s3][1], c = s_sc[type][s3][2];
        float m = fmaxf(a, fmaxf(b, c));
        float ea = expf(a - m), eb = expf(b - m), ec = expf(c - m);
        float inv = 0.0625f / (ea + eb + ec);
        s_sc[type][s3][0] = ea * inv; s_sc[type][s3][1] = eb * inv; s_sc[type][s3][2] = ec * inv;
    }
    __syncthreads();

    for (int idx = tid; idx < 3072; idx += 256) {
        int type = idx / 768, rem = idx % 768;
        int s3 = rem >> 8, d = rem & 255;
        int xsel = (type == 0 || type == 3) ? 1 : 0;
        float v = s_sc[type][s3][0] * s_x[xsel][0][d]
                + s_sc[type][s3][1] * s_x[xsel][1][d]
                + s_sc[type][s3][2] * s_x[xsel][2][d];
        float* dst = (type < 2) ? cat1 : cat2;
        dst[base2 + (size_t)s3 * 512 + ((type & 1) ? 256 : 0) + d] =
            __uint_as_float(tf32r(v));
    }
}

// ---------------- classifier (z-batched) ----------------
struct CLSB { const float* W1[2]; const float* W2[2]; };

__global__ void __launch_bounds__(256) cls_kernel(
    const float* __restrict__ Fbase, CLSB P, float* __restrict__ Pbase)
{
    __shared__ float s_f[8][128];
    __shared__ float s_w1[32][129];
    __shared__ float s_w2[320];
    __shared__ float s_h[8][32];
    const int z = blockIdx.y;
    const float* F = Fbase + (size_t)z * Bn * LAT;
    const float* W1 = P.W1[z];
    const float* W2 = P.W2[z];
    float* Pout = Pbase + (size_t)z * Bn * 10;

    const int tid = threadIdx.x;
    const int r0 = blockIdx.x * 8;
    for (int idx = tid; idx < 1024; idx += 256) s_f[idx >> 7][idx & 127] = F[(size_t)r0 * 128 + idx];
    for (int idx = tid; idx < 4096; idx += 256) s_w1[idx >> 7][idx & 127] = W1[idx];
    for (int idx = tid; idx < 320; idx += 256) s_w2[idx] = W2[idx];
    __syncthreads();
    const int w = tid >> 5, lane = tid & 31;
    float h = 0.0f;
#pragma unroll 8
    for (int d = 0; d < 128; d++) h = fmaf(s_f[w][d], s_w1[lane][d], h);
    s_h[w][lane] = fmaxf(h, 0.0f);
    __syncwarp();
    if (lane < 10) {
        float p = 0.0f;
#pragma unroll
        for (int k = 0; k < 32; k++) p = fmaf(s_h[w][k], s_w2[lane * 32 + k], p);
        Pout[(size_t)(r0 + w) * 10 + lane] = p;
    }
}

// ---------------- host ----------------
extern "C" void kernel_launch(void* const* d_in, const int* in_sizes, int n_in,
                              void* d_out, int out_size)
{
    const float* img    = (const float*)d_in[0];
    const float* audio  = (const float*)d_in[1];
    const float* vis_W  = (const float*)d_in[2];
    const float* vis_b  = (const float*)d_in[3];
    const float* aud_W  = (const float*)d_in[4];
    const float* aud_b  = (const float*)d_in[5];
    const float* msv_W  = (const float*)d_in[6];
    const float* msv_b  = (const float*)d_in[7];
    const float* msa_W  = (const float*)d_in[8];
    const float* msa_b  = (const float*)d_in[9];
    const float* mmfaW  = (const float*)d_in[10];
    const float* mmfaB  = (const float*)d_in[11];
    const float* bilW   = (const float*)d_in[12];
    const float* t_c    = (const float*)d_in[13];
    const float* out_W1 = (const float*)d_in[14];
    const float* out_b1 = (const float*)d_in[15];
    const float* out_W2 = (const float*)d_in[16];
    const float* out_b2 = (const float*)d_in[17];
    const float* clsvW1 = (const float*)d_in[18];
    const float* clsvW2 = (const float*)d_in[19];
    const float* clsaW1 = (const float*)d_in[20];
    const float* clsaW2 = (const float*)d_in[21];

    float* S = nullptr;
    cudaGetSymbolAddress((void**)&S, g_scratch);
    float* p_bf = nullptr;
    cudaGetSymbolAddress((void**)&p_bf, g_bias_fused);
    __half* p_Wh = nullptr;
    cudaGetSymbolAddress((void**)&p_Wh, g_Wh);

    float* p_vis  = S;
    float* p_aud  = p_vis + N_BE;
    float* p_vms  = p_aud + N_BE;
    float* p_ams  = p_vms + N_BSD;
    float* p_qkv  = p_ams + N_BSD;        // [3072][512]
    float* p_qka  = p_qkv + 2 * N_BSD;    // [3072][512]
    float* p_cat1 = p_qka + 2 * N_BSD;    // [3072][512]
    float* p_cat2 = p_cat1 + 2 * N_BSD;   // [3072][512]
    float* p_cva  = p_cat2 + 2 * N_BSD;
    float* p_cav  = p_cva + N_BSD;
    float* p_bp   = p_cav + N_BSD;        // 3 x [3072][256]
    float* p_xv   = p_bp  + 4 * N_BSD;
    float* p_xa   = p_xv  + N_BSD;
    float* p_ov   = p_xa  + N_BSD;        // ov/oa contiguous -> [2048][768]
    float* p_oa   = p_ov  + N_BSD;
    float* p_h    = p_oa  + N_BSD;        // [2048][512]
    // RNA-pre-rounded weight copies
    float* wr_mmfa = p_h + (size_t)2 * Bn * OUT1;
    float* wr_msv  = wr_mmfa + 2097152;
    float* wr_msa  = wr_msv + 786432;
    float* wr_o1   = wr_msa + 786432;
    float* wr_o2   = wr_o1 + 393216;

    const int nBlk = (int)(N_BSD / 256);

    cudaFuncSetAttribute(bilinear7_kernel,
                         cudaFuncAttributeMaxDynamicSharedMemorySize, BIL7_SMEM_BYTES);

    fuse_bias_kernel<<<1, 256>>>(mmfaB, p_bf);
    wconv_kernel<<<16384, 256>>>(bilW, p_Wh);
    wround_kernel<<<2048, 256>>>(mmfaW, wr_mmfa);
    wround_kernel<<<768, 256>>>(msv_W, wr_msv);
    wround_kernel<<<768, 256>>>(msa_W, wr_msa);
    wround_kernel<<<384, 256>>>(out_W1, wr_o1);
    wround_kernel<<<64, 256>>>(out_W2, wr_o2);
    float* p_b45 = p_bf;
    float* p_b67 = p_bf + 256;

    auto run_mmfa = [&](const float* xv, const float* xa,
                        const float* mv, const float* ma, float* o1, float* o2) {
        GB qk;
        qk.A[0] = xv;  qk.W[0] = wr_mmfa + 0 * 65536; qk.W2[0] = wr_mmfa + 2 * 65536;
        qk.b1[0] = mmfaB + 0 * 256; qk.b2[0] = mmfaB + 2 * 256; qk.E[0] = xv;  qk.C[0] = p_qkv;
        qk.A[1] = xa;  qk.W[1] = wr_mmfa + 1 * 65536; qk.W2[1] = wr_mmfa + 3 * 65536;
        qk.b1[1] = mmfaB + 1 * 256; qk.b2[1] = mmfaB + 3 * 256; qk.E[1] = xa;  qk.C[1] = p_qka;
        mma_gemm_kernel<<<dim3(512 / 64, M3 / 128, 2), 256>>>(qk, M3, 512, Dd, 256, 8, 0, 0);

        attn_kernel<<<Bn, 256>>>(xv, xa, p_qkv, p_qka, p_cat1, p_cat2);

        GB cc;
        cc.A[0] = p_cat1; cc.W[0] = wr_mmfa + 4 * 65536; cc.W2[0] = wr_mmfa + 5 * 65536;
        cc.b1[0] = p_b45; cc.b2[0] = p_b45; cc.E[0] = p_cat1; cc.C[0] = p_cva;
        cc.A[1] = p_cat2; cc.W[1] = wr_mmfa + 6 * 65536; cc.W2[1] = wr_mmfa + 7 * 65536;
        cc.b1[1] = p_b67; cc.b2[1] = p_b67; cc.E[1] = p_cat2; cc.C[1] = p_cav;
        mma_gemm_kernel<<<dim3(256 / 64, M3 / 128, 2), 256>>>(cc, M3, Dd, 512, 256, 4 | 16, 512, 256);

        bilinear7_kernel<<<dim3(24, 4, 3), 256, BIL7_SMEM_BYTES>>>(p_cva, p_cav, p_Wh, p_bp);
        bil_finish_kernel<<<nBlk, 256>>>(p_bp, xv, xa, t_c, mv, ma, o1, o2);
    };

    // encoders (vis||aud) fp32 SIMT with register prefetch
    {
        GB32 e;
        e.A[0] = img;   e.W[0] = vis_W; e.b[0] = vis_b; e.C[0] = p_vis; e.K[0] = 4096;
        e.A[1] = audio; e.W[1] = aud_W; e.b[1] = aud_b; e.C[1] = p_aud; e.K[1] = 1024;
        gemm_kernel<<<dim3(16, 8, 2), 256>>>(e, Bn, 1024, 1);
    }

    // multi-scale -> tf32 RNA tensor path (weights pre-rounded)
    {
        GB m;
        m.A[0] = p_vis; m.W[0] = m.W2[0] = wr_msv; m.b1[0] = m.b2[0] = msv_b;
        m.E[0] = p_vis; m.C[0] = p_vms;
        m.A[1] = p_aud; m.W[1] = m.W2[1] = wr_msa; m.b1[1] = m.b2[1] = msa_b;
        m.E[1] = p_aud; m.C[1] = p_ams;
        mma_gemm_kernel<<<dim3(SD / 64, Bn / 128, 2), 256>>>(m, Bn, SD, 1024, 1024, 1, 0, 0);
    }

    run_mmfa(p_vms, p_ams, p_vms, p_ams, p_xv, p_xa);
    run_mmfa(p_xv, p_xa, p_vms, p_ams, p_ov, p_oa);

    float* out = (float*)d_out;
    float* fv = out;
    float* fa = out + (size_t)Bn * LAT;
    float* pv = fa + (size_t)Bn * LAT;

    // out_layer M-batched over (ov||oa) -> (fv||fa)
    {
        GB o1;
        o1.A[0] = o1.A[1] = p_ov; o1.W[0] = o1.W[1] = wr_o1; o1.W2[0] = o1.W2[1] = wr_o1;
        o1.b1[0] = o1.b1[1] = out_b1; o1.b2[0] = o1.b2[1] = out_b1;
        o1.E[0] = o1.E[1] = p_ov; o1.C[0] = o1.C[1] = p_h;
        mma_gemm_kernel<<<dim3(OUT1 / 64, 2 * Bn / 128, 1), 256>>>(o1, 2 * Bn, OUT1, SD, SD, 1 | 32, 0, 0);

        GB o2;
        o2.A[0] = o2.A[1] = p_h; o2.W[0] = o2.W[1] = wr_o2; o2.W2[0] = o2.W2[1] = wr_o2;
        o2.b1[0] = o2.b1[1] = out_b2; o2.b2[0] = o2.b2[1] = out_b2;
        o2.E[0] = o2.E[1] = p_h; o2.C[0] = o2.C[1] = fv;
        mma_gemm_kernel<<<dim3(LAT / 64, 2 * Bn / 128, 1), 256>>>(o2, 2 * Bn, LAT, OUT1, OUT1, 16, 0, 0);
    }

    // classifiers batched (z=2)
    {
        CLSB cb;
        cb.W1[0] = clsvW1; cb.W2[0] = clsvW2;
        cb.W1[1] = clsaW1; cb.W2[1] = clsaW2;
        cls_kernel<<<dim3(Bn / 8, 2), 256>>>(fv, cb, pv);
    }
}

// round 16
// speedup vs baseline: 1.3939x; 1.0640x over previous
#include <cuda_runtime.h>
#include <cuda_fp16.h>
#include <math.h>
#include <stdint.h>

// ---------------- problem constants ----------------
static constexpr int Bn   = 1024;
static constexpr int M3   = 3072;   // B*S
static constexpr int Dd   = 256;
static constexpr int SD   = 768;
static constexpr int OUT1 = 512;
static constexpr int LAT  = 128;

static constexpr size_t N_BE  = (size_t)Bn * 1024;
static constexpr size_t N_BSD = (size_t)M3 * Dd;     // 786432

__device__ float g_scratch[2 * N_BE + 26 * N_BSD + (size_t)Bn * OUT1];
__device__ float g_bias_fused[512];            // [0:256)=b4+b5, [256:512)=b6+b7
__device__ __half g_Wh[16777216];              // bil_W in fp16 (32MB)
__device__ __half g_hbuf[15400000];            // fp16 activations + weights

__device__ __forceinline__ float sigm(float x) { return 1.0f / (1.0f + expf(-x)); }

__device__ __forceinline__ void mma_f16(float& c0, float& c1, float& c2, float& c3,
                                        unsigned a0, unsigned a1, unsigned a2, unsigned a3,
                                        unsigned b0, unsigned b1) {
    asm("mma.sync.aligned.m16n8k16.row.col.f32.f16.f16.f32 "
        "{%0,%1,%2,%3}, {%4,%5,%6,%7}, {%8,%9}, {%0,%1,%2,%3};"
        : "+f"(c0), "+f"(c1), "+f"(c2), "+f"(c3)
        : "r"(a0), "r"(a1), "r"(a2), "r"(a3), "r"(b0), "r"(b1));
}

__device__ __forceinline__ void cpa16(void* smem_dst, const void* gsrc) {
    unsigned sa = (unsigned)__cvta_generic_to_shared(smem_dst);
    asm volatile("cp.async.cg.shared.global [%0], [%1], 16;" :: "r"(sa), "l"(gsrc));
}

// ---------------- helpers ----------------
__global__ void fuse_bias_kernel(const float* __restrict__ b, float* __restrict__ o)
{
    int i = threadIdx.x;
    o[i]       = b[4 * 256 + i] + b[5 * 256 + i];
    o[256 + i] = b[6 * 256 + i] + b[7 * 256 + i];
}

// generic fp32 -> fp16 converter (weights)
__global__ void wconv_kernel(const float* __restrict__ W, __half* __restrict__ Wh)
{
    size_t i = ((size_t)blockIdx.x * 256 + threadIdx.x) * 4;
    float4 v = *(const float4*)(W + i);
    *(__half2*)(Wh + i)     = __floats2half2_rn(v.x, v.y);
    *(__half2*)(Wh + i + 2) = __floats2half2_rn(v.z, v.w);
}

// ---------------- fp32 SIMT GEMM, z-batched (encoders), dual fp32+fp16 output ----
struct GB32 {
    const float* A[2]; const float* W[2]; const float* b[2];
    float* C[2]; __half* Ch[2]; int K[2];
};

__global__ void __launch_bounds__(256) gemm_kernel(GB32 P, int M, int N, int flags)
{
    __shared__ __align__(16) float As[16][132];
    __shared__ __align__(16) float Ws[16][68];
    const int z = blockIdx.z;
    const float* A = P.A[z];
    const float* W = P.W[z];
    const float* bias = P.b[z];
    float* C = P.C[z];
    __half* Ch = P.Ch[z];
    const int K = P.K[z];

    const int tid = threadIdx.x;
    const int tx = tid & 15, ty = tid >> 4;
    const int m0 = blockIdx.y * 128, n0 = blockIdx.x * 64;
    const int lrow = tid >> 2, lk = (tid & 3) << 2;

    const float* Ag0 = A + (size_t)(m0 + lrow) * K + lk;
    const float* Ag1 = A + (size_t)(m0 + lrow + 64) * K + lk;
    const float* Wg  = W + (size_t)(n0 + lrow) * K + lk;

    float4 a0 = *(const float4*)(Ag0);
    float4 a1 = *(const float4*)(Ag1);
    float4 w0 = *(const float4*)(Wg);

    float acc[8][4] = {};
    for (int kt = 0; kt < K; kt += 16) {
        As[lk + 0][lrow] = a0.x; As[lk + 1][lrow] = a0.y;
        As[lk + 2][lrow] = a0.z; As[lk + 3][lrow] = a0.w;
        As[lk + 0][lrow + 64] = a1.x; As[lk + 1][lrow + 64] = a1.y;
        As[lk + 2][lrow + 64] = a1.z; As[lk + 3][lrow + 64] = a1.w;
        Ws[lk + 0][lrow] = w0.x; Ws[lk + 1][lrow] = w0.y;
        Ws[lk + 2][lrow] = w0.z; Ws[lk + 3][lrow] = w0.w;
        __syncthreads();
        if (kt + 16 < K) {
            a0 = *(const float4*)(Ag0 + kt + 16);
            a1 = *(const float4*)(Ag1 + kt + 16);
            w0 = *(const float4*)(Wg + kt + 16);
        }
#pragma unroll
        for (int k = 0; k < 16; k++) {
            float ar[8];
            *(float4*)&ar[0] = *(const float4*)&As[k][ty * 8];
            *(float4*)&ar[4] = *(const float4*)&As[k][ty * 8 + 4];
            float4 b = *(const float4*)&Ws[k][tx * 4];
#pragma unroll
            for (int i = 0; i < 8; i++) {
                acc[i][0] = fmaf(ar[i], b.x, acc[i][0]);
                acc[i][1] = fmaf(ar[i], b.y, acc[i][1]);
                acc[i][2] = fmaf(ar[i], b.z, acc[i][2]);
                acc[i][3] = fmaf(ar[i], b.w, acc[i][3]);
            }
        }
        __syncthreads();
    }
#pragma unroll
    for (int i = 0; i < 8; i++) {
        int row = m0 + ty * 8 + i;
#pragma unroll
        for (int j = 0; j < 4; j++) {
            int col = n0 + tx * 4 + j;
            float v = acc[i][j] + bias[col];
            if (flags & 1) v = fmaxf(v, 0.0f);
            C[(size_t)row * N + col] = v;
            if (flags & 2) Ch[(size_t)row * N + col] = __float2half_rn(v);
        }
    }
}

// ---------------- fp16 tensor GEMM: 128x64 tile, k-tile 32, 3-stage cp.async ---------
// flags: bit0 relu ; bit2 sigmul: out = sigm(v * Eh[row*eld + eoff + col]) ;
//        bit3 N-split (W rows < Kx from W, else W2; biases b1/b2) ; bit6 write fp16 copy
struct GH {
    const __half* A[2]; const __half* W[2]; const __half* W2[2];
    const float* b1[2]; const float* b2[2]; const __half* E[2];
    float* C[2]; __half* Ch[2];
};

__global__ void __launch_bounds__(256) mma16_kernel(
    GH P, int M, int N, int K, int Kx, int flags, int eld, int eoff)
{
    __shared__ __align__(16) __half As[3][128][40];   // 30720 B
    __shared__ __align__(16) __half Ws[3][64][40];    // 15360 B
    const int z = blockIdx.z;
    const __half* A = P.A[z];
    const __half* W = P.W[z];
    const __half* W2 = P.W2[z];
    const float* bias = P.b1[z];
    const float* bias2 = P.b2[z];
    const __half* E = P.E[z];
    float* C = P.C[z];
    __half* Ch = P.Ch[z];

    const int tid = threadIdx.x;
    const int lane = tid & 31, wid = tid >> 5;
    const int wm = wid >> 1, wn = wid & 1;     // 4m x 2n
    const int m0 = blockIdx.y * 128, n0 = blockIdx.x * 64;
    const int c4 = lane & 3, lr = lane >> 2;
    const int Kb = K - Kx;
    const bool nsplit = (flags & 8) != 0;

    float c[2][4][4];
#pragma unroll
    for (int mt = 0; mt < 2; mt++)
#pragma unroll
        for (int nt = 0; nt < 4; nt++)
#pragma unroll
            for (int e = 0; e < 4; e++) c[mt][nt][e] = 0.0f;

    auto issue_tile = [&](int kt) {
        int buf = kt % 3;
        int kbase = kt * 32;
#pragma unroll
        for (int u = 0; u < 2; u++) {
            int chunk = tid + 256 * u;          // 0..511
            int row = chunk >> 2, ch = chunk & 3;
            cpa16(&As[buf][row][ch * 8], A + (size_t)(m0 + row) * K + kbase + ch * 8);
        }
        {
            int row = tid >> 2, ch = tid & 3;   // 0..63 x 0..3
            int k = kbase + ch * 8;
            const __half* ws;
            if (nsplit) {
                int n = n0 + row;
                ws = (n < Kx) ? (W + (size_t)n * K + k) : (W2 + (size_t)(n - Kx) * K + k);
            } else {
                ws = (k < Kx) ? (W + (size_t)(n0 + row) * Kx + k)
                              : (W2 + (size_t)(n0 + row) * Kb + (k - Kx));
            }
            cpa16(&Ws[buf][row][ch * 8], ws);
        }
        asm volatile("cp.async.commit_group;");
    };

    const int ktiles = K >> 5;
    issue_tile(0);
    if (ktiles > 1) issue_tile(1);

    const int rbB = wm * 32 + lr;
    for (int kt = 0; kt < ktiles; kt++) {
        if (kt + 1 < ktiles) asm volatile("cp.async.wait_group 1;" ::: "memory");
        else                 asm volatile("cp.async.wait_group 0;" ::: "memory");
        __syncthreads();
        if (kt + 2 < ktiles) issue_tile(kt + 2);
        const int buf = kt % 3;
#pragma unroll
        for (int kk = 0; kk < 32; kk += 16) {
            unsigned a[2][4];
#pragma unroll
            for (int mt = 0; mt < 2; mt++) {
                int rb = rbB + mt * 16;
                a[mt][0] = *(const unsigned*)&As[buf][rb][kk + 2 * c4];
                a[mt][1] = *(const unsigned*)&As[buf][rb + 8][kk + 2 * c4];
                a[mt][2] = *(const unsigned*)&As[buf][rb][kk + 2 * c4 + 8];
                a[mt][3] = *(const unsigned*)&As[buf][rb + 8][kk + 2 * c4 + 8];
            }
#pragma unroll
            for (int nt = 0; nt < 4; nt++) {
                int nb = wn * 32 + nt * 8 + lr;
                unsigned b0 = *(const unsigned*)&Ws[buf][nb][kk + 2 * c4];
                unsigned b1 = *(const unsigned*)&Ws[buf][nb][kk + 2 * c4 + 8];
#pragma unroll
                for (int mt = 0; mt < 2; mt++)
                    mma_f16(c[mt][nt][0], c[mt][nt][1], c[mt][nt][2], c[mt][nt][3],
                            a[mt][0], a[mt][1], a[mt][2], a[mt][3], b0, b1);
            }
        }
    }

#pragma unroll
    for (int mt = 0; mt < 2; mt++) {
#pragma unroll
        for (int nt = 0; nt < 4; nt++) {
            int row = m0 + wm * 32 + mt * 16 + lr;
            int col = n0 + wn * 32 + nt * 8 + c4 * 2;
#pragma unroll
            for (int e = 0; e < 4; e++) {
                int rr = row + (e >> 1) * 8;
                int cc = col + (e & 1);
                float bv = nsplit ? ((cc < Kx) ? bias[cc] : bias2[cc - Kx]) : bias[cc];
                float v = c[mt][nt][e] + bv;
                if (flags & 1) v = fmaxf(v, 0.0f);
                if (flags & 4) v = sigm(v * __half2float(E[(size_t)rr * eld + eoff + cc]));
                C[(size_t)rr * N + cc] = v;
                if (flags & 64) Ch[(size_t)rr * N + cc] = __float2half_rn(v);
            }
        }
    }
}

// ---------------- fp16 bilinear v7b (round-15 passing version, unchanged) ----
static constexpr int BIL7_SMEM_BYTES = (128 * 264 + 3 * 64 * 72) * 2;

__global__ void __launch_bounds__(256) bilinear7_kernel(
    const float* __restrict__ cva, const float* __restrict__ cav,
    const __half* __restrict__ Wh, float* __restrict__ part)
{
    extern __shared__ __half sh[];
    __half* s_cav = sh;                // [128][264]
    __half* s_W   = sh + 128 * 264;    // [3][64][72]

    const int tid = threadIdx.x;
    const int lane = tid & 31, wid = tid >> 5;
    const int wm = wid >> 1, wn = wid & 1;   // 4m(32) x 2n(32)
    const int g = lane >> 2, q = lane & 3;
    const int r0 = blockIdx.x * 128, o0 = blockIdx.y * 64;
    const int z = blockIdx.z;
    const int iStart = (z < 2) ? z * 85 : 170;   // 85 + 85 + 86 = 256
    const int iCnt   = (z < 2) ? 85 : 86;
    const int T = iCnt * 4;

    for (int f = tid; f < 8192; f += 256) {
        int row = f >> 6, q4 = f & 63;
        float4 w = *(const float4*)(cav + (size_t)(r0 + row) * 256 + q4 * 4);
        __half* d = s_cav + row * 264 + q4 * 4;
        *(__half2*)(d)     = __floats2half2_rn(w.x, w.y);
        *(__half2*)(d + 2) = __floats2half2_rn(w.z, w.w);
    }

    float c[2][4][4];
#pragma unroll
    for (int mt = 0; mt < 2; mt++)
#pragma unroll
        for (int nt = 0; nt < 4; nt++)
#pragma unroll
            for (int e = 0; e < 4; e++) c[mt][nt][e] = 0.0f;

    auto issue_tile = [&](int t) {
        int i = iStart + (t >> 2), h = t & 3;
        __half* dst0 = s_W + (t % 3) * 64 * 72;
#pragma unroll
        for (int u = 0; u < 2; u++) {
            int cidx = tid + 256 * u;          // 0..511
            int o = cidx >> 3, ch = cidx & 7;
            const __half* src = Wh + (size_t)(o0 + o) * 65536 + (size_t)i * 256 + h * 64 + ch * 8;
            cpa16(dst0 + o * 72 + ch * 8, src);
        }
        asm volatile("cp.async.commit_group;");
    };

    issue_tile(0);
    issue_tile(1);

    const int rb = wm * 32 + g;
    const float* cvaB = cva + (size_t)r0 * 256;

    float spf[4];
#pragma unroll
    for (int mt = 0; mt < 4; mt++)
        spf[mt] = cvaB[(size_t)(rb + mt * 8) * 256 + iStart];
    __half2 s[4];
#pragma unroll
    for (int u = 0; u < 4; u++) s[u] = __half2half2(__float2half_rn(spf[u]));

    for (int t = 0; t < T; t++) {
        if (t + 1 < T) asm volatile("cp.async.wait_group 1;" ::: "memory");
        else           asm volatile("cp.async.wait_group 0;" ::: "memory");
        __syncthreads();
        if (t + 2 < T) issue_tile(t + 2);

        const __half* wbuf = s_W + (t % 3) * 64 * 72;
        const int h = t & 3;
        const bool advance = (h == 3) && (t + 1 < T);
        if (advance) {
            int ig2 = iStart + ((t + 1) >> 2);
#pragma unroll
            for (int mt = 0; mt < 4; mt++)
                spf[mt] = cvaB[(size_t)(rb + mt * 8) * 256 + ig2];
        }

#pragma unroll
        for (int jc = 0; jc < 4; jc++) {
            const int jlo = h * 64 + jc * 16 + 2 * q;
            const int jhi = jlo + 8;
            __half2 a[2][4];
#pragma unroll
            for (int mt = 0; mt < 2; mt++) {
                int r1 = rb + mt * 16, r2 = r1 + 8;
                a[mt][0] = __hmul2(*(__half2*)&s_cav[r1 * 264 + jlo], s[2 * mt]);
                a[mt][1] = __hmul2(*(__half2*)&s_cav[r2 * 264 + jlo], s[2 * mt + 1]);
                a[mt][2] = __hmul2(*(__half2*)&s_cav[r1 * 264 + jhi], s[2 * mt]);
                a[mt][3] = __hmul2(*(__half2*)&s_cav[r2 * 264 + jhi], s[2 * mt + 1]);
            }
            const int kloc = jc * 16;
#pragma unroll
            for (int nt = 0; nt < 4; nt++) {
                int oc = wn * 32 + nt * 8 + g;
                unsigned b0 = *(const unsigned*)&wbuf[oc * 72 + kloc + 2 * q];
                unsigned b1 = *(const unsigned*)&wbuf[oc * 72 + kloc + 2 * q + 8];
#pragma unroll
                for (int mt = 0; mt < 2; mt++)
                    mma_f16(c[mt][nt][0], c[mt][nt][1], c[mt][nt][2], c[mt][nt][3],
                            *(unsigned*)&a[mt][0], *(unsigned*)&a[mt][1],
                            *(unsigned*)&a[mt][2], *(unsigned*)&a[mt][3], b0, b1);
            }
        }
        if (advance) {
#pragma unroll
            for (int u = 0; u < 4; u++) s[u] = __half2half2(__float2half_rn(spf[u]));
        }
    }

    float* P = part + (size_t)z * N_BSD;
#pragma unroll
    for (int mt = 0; mt < 2; mt++) {
#pragma unroll
        for (int nt = 0; nt < 4; nt++) {
            int row = r0 + wm * 32 + mt * 16 + g;
            int col = o0 + wn * 32 + nt * 8 + q * 2;
            float* d0 = P + (size_t)row * 256 + col;
            float* d1 = P + (size_t)(row + 8) * 256 + col;
            d0[0] = c[mt][nt][0]; d0[1] = c[mt][nt][1];
            d1[0] = c[mt][nt][2]; d1[1] = c[mt][nt][3];
        }
    }
}

// finish: j = sigm(sum of 3 partials); m = tc*j*xv + (1-j)*xa; outputs fp32 + fp16
__global__ void bil_finish_kernel(const float* __restrict__ part,
                                  const float* __restrict__ xv, const float* __restrict__ xa,
                                  const float* __restrict__ tcp,
                                  const float* __restrict__ mv, const float* __restrict__ ma,
                                  float* __restrict__ o1, float* __restrict__ o2,
                                  __half* __restrict__ o1h, __half* __restrict__ o2h)
{
    int i = blockIdx.x * 256 + threadIdx.x;
    float s = part[i] + part[i + N_BSD] + part[i + 2 * N_BSD];
    float j = sigm(s);
    float m = (*tcp) * j * xv[i] + (1.0f - j) * xa[i];
    float v1 = m * mv[i];
    float v2 = m * ma[i];
    o1[i] = v1;  o2[i] = v2;
    o1h[i] = __float2half_rn(v1);
    o2h[i] = __float2half_rn(v2);
}

// ---------------- attention (writes cat as fp16) ----------------
__global__ void __launch_bounds__(256) attn_kernel(
    const float* __restrict__ xv, const float* __restrict__ xa,
    const float* __restrict__ qkv_v, const float* __restrict__ qkv_a,
    __half* __restrict__ cat1, __half* __restrict__ cat2)
{
    __shared__ float s_x[2][3][256];
    __shared__ float s_q[2][3][256];
    __shared__ float s_k[2][3][256];
    __shared__ float s_sc[4][3][3];
    const int tid = threadIdx.x;
    const size_t base = (size_t)blockIdx.x * 768;
    const size_t base2 = (size_t)blockIdx.x * 1536;
    const size_t qbase = (size_t)blockIdx.x * 3 * 512;

    float* fx = &s_x[0][0][0];
    float* fq = &s_q[0][0][0];
    float* fk = &s_k[0][0][0];
    for (int idx = tid; idx < 768; idx += 256) {
        int s3 = idx >> 8, d = idx & 255;
        size_t qoff = qbase + (size_t)s3 * 512 + d;
        fx[idx] = xv[base + idx]; fx[768 + idx] = xa[base + idx];
        fq[idx] = qkv_v[qoff];        fq[768 + idx] = qkv_a[qoff];
        fk[idx] = qkv_v[qoff + 256];  fk[768 + idx] = qkv_a[qoff + 256];
    }
    __syncthreads();

    const int w = tid >> 5, lane = tid & 31;
    for (int task = w; task < 36; task += 8) {
        int type = task / 9, rem = task % 9, s3 = rem / 3, t3 = rem % 3;
        int qsel = type >> 1;
        int ksel = (type == 0 || type == 3) ? 1 : 0;
        float sum = 0.0f;
        for (int d = lane; d < 256; d += 32) sum += s_q[qsel][s3][d] * s_k[ksel][t3][d];
#pragma unroll
        for (int off = 16; off; off >>= 1) sum += __shfl_down_sync(0xffffffffu, sum, off);
        if (lane == 0) s_sc[type][s3][t3] = sum;
    }
    __syncthreads();

    if (tid < 12) {
        int type = tid / 3, s3 = tid % 3;
        float a = s_sc[type][s3][0], b = s_sc[type][s3][1], c = s_sc[type][s3][2];
        float m = fmaxf(a, fmaxf(b, c));
        float ea = expf(a - m), eb = expf(b - m), ec = expf(c - m);
        float inv = 0.0625f / (ea + eb + ec);
        s_sc[type][s3][0] = ea * inv; s_sc[type][s3][1] = eb * inv; s_sc[type][s3][2] = ec * inv;
    }
    __syncthreads();

    for (int idx = tid; idx < 3072; idx += 256) {
        int type = idx / 768, rem = idx % 768;
        int s3 = rem >> 8, d = rem & 255;
        int xsel = (type == 0 || type == 3) ? 1 : 0;
        float v = s_sc[type][s3][0] * s_x[xsel][0][d]
                + s_sc[type][s3][1] * s_x[xsel][1][d]
                + s_sc[type][s3][2] * s_x[xsel][2][d];
        __half* dst = (type < 2) ? cat1 : cat2;
        dst[base2 + (size_t)s3 * 512 + ((type & 1) ? 256 : 0) + d] = __float2half_rn(v);
    }
}

// ---------------- classifier (z-batched) ----------------
struct CLSB { const float* W1[2]; const float* W2[2]; };

__global__ void __launch_bounds__(256) cls_kernel(
    const float* __restrict__ Fbase, CLSB P, float* __restrict__ Pbase)
{
    __shared__ float s_f[8][128];
    __shared__ float s_w1[32][129];
    __shared__ float s_w2[320];
    __shared__ float s_h[8][32];
    const int z = blockIdx.y;
    const float* F = Fbase + (size_t)z * Bn * LAT;
    const float* W1 = P.W1[z];
    const float* W2 = P.W2[z];
    float* Pout = Pbase + (size_t)z * Bn * 10;

    const int tid = threadIdx.x;
    const int r0 = blockIdx.x * 8;
    for (int idx = tid; idx < 1024; idx += 256) s_f[idx >> 7][idx & 127] = F[(size_t)r0 * 128 + idx];
    for (int idx = tid; idx < 4096; idx += 256) s_w1[idx >> 7][idx & 127] = W1[idx];
    for (int idx = tid; idx < 320; idx += 256) s_w2[idx] = W2[idx];
    __syncthreads();
    const int w = tid >> 5, lane = tid & 31;
    float h = 0.0f;
#pragma unroll 8
    for (int d = 0; d < 128; d++) h = fmaf(s_f[w][d], s_w1[lane][d], h);
    s_h[w][lane] = fmaxf(h, 0.0f);
    __syncwarp();
    if (lane < 10) {
        float p = 0.0f;
#pragma unroll
        for (int k = 0; k < 32; k++) p = fmaf(s_h[w][k], s_w2[lane * 32 + k], p);
        Pout[(size_t)(r0 + w) * 10 + lane] = p;
    }
}

// ---------------- host ----------------
extern "C" void kernel_launch(void* const* d_in, const int* in_sizes, int n_in,
                              void* d_out, int out_size)
{
    const float* img    = (const float*)d_in[0];
    const float* audio  = (const float*)d_in[1];
    const float* vis_W  = (const float*)d_in[2];
    const float* vis_b  = (const float*)d_in[3];
    const float* aud_W  = (const float*)d_in[4];
    const float* aud_b  = (const float*)d_in[5];
    const float* msv_W  = (const float*)d_in[6];
    const float* msv_b  = (const float*)d_in[7];
    const float* msa_W  = (const float*)d_in[8];
    const float* msa_b  = (const float*)d_in[9];
    const float* mmfaW  = (const float*)d_in[10];
    const float* mmfaB  = (const float*)d_in[11];
    const float* bilW   = (const float*)d_in[12];
    const float* t_c    = (const float*)d_in[13];
    const float* out_W1 = (const float*)d_in[14];
    const float* out_b1 = (const float*)d_in[15];
    const float* out_W2 = (const float*)d_in[16];
    const float* out_b2 = (const float*)d_in[17];
    const float* clsvW1 = (const float*)d_in[18];
    const float* clsvW2 = (const float*)d_in[19];
    const float* clsaW1 = (const float*)d_in[20];
    const float* clsaW2 = (const float*)d_in[21];

    float* S = nullptr;
    cudaGetSymbolAddress((void**)&S, g_scratch);
    float* p_bf = nullptr;
    cudaGetSymbolAddress((void**)&p_bf, g_bias_fused);
    __half* p_Wh = nullptr;
    cudaGetSymbolAddress((void**)&p_Wh, g_Wh);
    __half* H = nullptr;
    cudaGetSymbolAddress((void**)&H, g_hbuf);

    // fp32 scratch
    float* p_vis  = S;
    float* p_aud  = p_vis + N_BE;
    float* p_vms  = p_aud + N_BE;
    float* p_ams  = p_vms + N_BSD;
    float* p_qkv  = p_ams + N_BSD;        // [3072][512]
    float* p_qka  = p_qkv + 2 * N_BSD;    // [3072][512]
    float* p_cva  = p_qka + 2 * N_BSD;
    float* p_cav  = p_cva + N_BSD;
    float* p_bp   = p_cav + N_BSD;        // 3 x [3072][256]
    float* p_xv   = p_bp  + 3 * N_BSD;
    float* p_xa   = p_xv  + N_BSD;
    float* p_ov   = p_xa  + N_BSD;
    float* p_oa   = p_ov  + N_BSD;
    float* p_h    = p_oa  + N_BSD;        // [2048][512]

    // fp16 scratch (activations + weights)
    __half* h_vis  = H;                        // [1024][1024]
    __half* h_aud  = h_vis + N_BE;
    __half* h_vms  = h_aud + N_BE;             // [3072][256]
    __half* h_ams  = h_vms + N_BSD;
    __half* h_xv   = h_ams + N_BSD;
    __half* h_xa   = h_xv + N_BSD;
    __half* h_cat1 = h_xa + N_BSD;             // [3072][512]
    __half* h_cat2 = h_cat1 + 2 * N_BSD;
    __half* h_ov   = h_cat2 + 2 * N_BSD;       // ov/oa contiguous [2048][768]
    __half* h_oa   = h_ov + N_BSD;
    __half* h_h    = h_oa + N_BSD;             // [2048][512]
    __half* wh_mmfa = h_h + (size_t)2 * Bn * OUT1;
    __half* wh_msv  = wh_mmfa + 2097152;
    __half* wh_msa  = wh_msv + 786432;
    __half* wh_o1   = wh_msa + 786432;
    __half* wh_o2   = wh_o1 + 393216;

    const int nBlk = (int)(N_BSD / 256);

    cudaFuncSetAttribute(bilinear7_kernel,
                         cudaFuncAttributeMaxDynamicSharedMemorySize, BIL7_SMEM_BYTES);

    // prep: bias fusion + all weight conversions to fp16
    fuse_bias_kernel<<<1, 256>>>(mmfaB, p_bf);
    wconv_kernel<<<16384, 256>>>(bilW, p_Wh);
    wconv_kernel<<<2048, 256>>>(mmfaW, wh_mmfa);
    wconv_kernel<<<768, 256>>>(msv_W, wh_msv);
    wconv_kernel<<<768, 256>>>(msa_W, wh_msa);
    wconv_kernel<<<384, 256>>>(out_W1, wh_o1);
    wconv_kernel<<<64, 256>>>(out_W2, wh_o2);
    float* p_b45 = p_bf;
    float* p_b67 = p_bf + 256;

    auto run_mmfa = [&](const float* xv, const float* xa,
                        const __half* xvh, const __half* xah,
                        const float* mv, const float* ma,
                        float* o1, float* o2, __half* o1h, __half* o2h) {
        // q|k both modalities, N-split, fp16
        GH qk;
        qk.A[0] = xvh; qk.W[0] = wh_mmfa + 0 * 65536; qk.W2[0] = wh_mmfa + 2 * 65536;
        qk.b1[0] = mmfaB + 0 * 256; qk.b2[0] = mmfaB + 2 * 256; qk.E[0] = xvh;
        qk.C[0] = p_qkv; qk.Ch[0] = nullptr;
        qk.A[1] = xah; qk.W[1] = wh_mmfa + 1 * 65536; qk.W2[1] = wh_mmfa + 3 * 65536;
        qk.b1[1] = mmfaB + 1 * 256; qk.b2[1] = mmfaB + 3 * 256; qk.E[1] = xah;
        qk.C[1] = p_qka; qk.Ch[1] = nullptr;
        mma16_kernel<<<dim3(512 / 64, M3 / 128, 2), 256>>>(qk, M3, 512, Dd, 256, 8, 0, 0);

        attn_kernel<<<Bn, 256>>>(xv, xa, p_qkv, p_qka, h_cat1, h_cat2);

        // cva|cav, K-split, sigmul epilogue, fp16
        GH cc;
        cc.A[0] = h_cat1; cc.W[0] = wh_mmfa + 4 * 65536; cc.W2[0] = wh_mmfa + 5 * 65536;
        cc.b1[0] = p_b45; cc.b2[0] = p_b45; cc.E[0] = h_cat1;
        cc.C[0] = p_cva; cc.Ch[0] = nullptr;
        cc.A[1] = h_cat2; cc.W[1] = wh_mmfa + 6 * 65536; cc.W2[1] = wh_mmfa + 7 * 65536;
        cc.b1[1] = p_b67; cc.b2[1] = p_b67; cc.E[1] = h_cat2;
        cc.C[1] = p_cav; cc.Ch[1] = nullptr;
        mma16_kernel<<<dim3(256 / 64, M3 / 128, 2), 256>>>(cc, M3, Dd, 512, 256, 4, 512, 256);

        bilinear7_kernel<<<dim3(24, 4, 3), 256, BIL7_SMEM_BYTES>>>(p_cva, p_cav, p_Wh, p_bp);
        bil_finish_kernel<<<nBlk, 256>>>(p_bp, xv, xa, t_c, mv, ma, o1, o2, o1h, o2h);
    };

    // encoders (vis||aud) fp32 SIMT, dual fp32+fp16 outputs
    {
        GB32 e;
        e.A[0] = img;   e.W[0] = vis_W; e.b[0] = vis_b; e.C[0] = p_vis; e.Ch[0] = h_vis; e.K[0] = 4096;
        e.A[1] = audio; e.W[1] = aud_W; e.b[1] = aud_b; e.C[1] = p_aud; e.Ch[1] = h_aud; e.K[1] = 1024;
        gemm_kernel<<<dim3(16, 8, 2), 256>>>(e, Bn, 1024, 1 | 2);
    }

    // multi-scale: fp16 GEMM, relu, dual outputs
    {
        GH m;
        m.A[0] = h_vis; m.W[0] = m.W2[0] = wh_msv; m.b1[0] = m.b2[0] = msv_b;
        m.E[0] = h_vis; m.C[0] = p_vms; m.Ch[0] = h_vms;
        m.A[1] = h_aud; m.W[1] = m.W2[1] = wh_msa; m.b1[1] = m.b2[1] = msa_b;
        m.E[1] = h_aud; m.C[1] = p_ams; m.Ch[1] = h_ams;
        mma16_kernel<<<dim3(SD / 64, Bn / 128, 2), 256>>>(m, Bn, SD, 1024, 1024, 1 | 64, 0, 0);
    }

    // MMfa 1: xv2 = M1*vms, xa2 = M1*ams ; MMfa 2: ov = M2*vms, oa = M2*ams
    run_mmfa(p_vms, p_ams, h_vms, h_ams, p_vms, p_ams, p_xv, p_xa, h_xv, h_xa);
    run_mmfa(p_xv, p_xa, h_xv, h_xa, p_vms, p_ams, p_ov, p_oa, h_ov, h_oa);

    float* out = (float*)d_out;
    float* fv = out;
    float* fa = out + (size_t)Bn * LAT;
    float* pv = fa + (size_t)Bn * LAT;

    // out_layer M-batched over (ov||oa) -> (fv||fa), fp16 path
    {
        GH o1;
        o1.A[0] = o1.A[1] = h_ov; o1.W[0] = o1.W[1] = wh_o1; o1.W2[0] = o1.W2[1] = wh_o1;
        o1.b1[0] = o1.b1[1] = out_b1; o1.b2[0] = o1.b2[1] = out_b1;
        o1.E[0] = o1.E[1] = h_ov; o1.C[0] = o1.C[1] = p_h; o1.Ch[0] = o1.Ch[1] = h_h;
        mma16_kernel<<<dim3(OUT1 / 64, 2 * Bn / 128, 1), 256>>>(o1, 2 * Bn, OUT1, SD, SD, 1 | 64, 0, 0);

        GH o2;
        o2.A[0] = o2.A[1] = h_h; o2.W[0] = o2.W[1] = wh_o2; o2.W2[0] = o2.W2[1] = wh_o2;
        o2.b1[0] = o2.b1[1] = out_b2; o2.b2[0] = o2.b2[1] = out_b2;
        o2.E[0] = o2.E[1] = h_h; o2.C[0] = o2.C[1] = fv; o2.Ch[0] = o2.Ch[1] = nullptr;
        mma16_kernel<<<dim3(LAT / 64, 2 * Bn / 128, 1), 256>>>(o2, 2 * Bn, LAT, OUT1, OUT1, 0, 0, 0);
    }

    // classifiers batched (z=2)
    {
        CLSB cb;
        cb.W1[0] = clsvW1; cb.W2[0] = clsvW2;
        cb.W1[1] = clsaW1; cb.W2[1] = clsaW2;
        cls_kernel<<<dim3(Bn / 8, 2), 256>>>(fv, cb, pv);
    }
}